// round 1
// baseline (speedup 1.0000x reference)
#include <cuda_runtime.h>
#include <cuda_bf16.h>
#include <math.h>

// Problem constants
#define BB 16
#define SS 16
#define VV 64
#define EE 64
#define HH 8
#define NL 4
#define DFF 2048
#define LL 1024         // S*V
#define DH 8            // E/H
#define ML (BB*LL)      // 16384 tokens

// ---------------- scratch buffers (device globals; no allocation) ----------------
__device__ float g_x[ML * EE];            // 4 MB  activations
__device__ float g_qkv[ML * 3 * EE];      // 12 MB
__device__ float g_attn[ML * EE];         // 4 MB
__device__ float g_tmp[ML * EE];          // 4 MB
__device__ float g_h[ML * DFF];           // 128 MB ffn hidden
__device__ unsigned char g_zero[ML];      // zero-token mask

// ---------------- embed: features->E, concat overlap/poi, W_comb, + pos/type ----------------
__global__ void embed_kernel(const float* __restrict__ features,
                             const int* __restrict__ overlap_tag,
                             const int* __restrict__ poi_id,
                             const float* __restrict__ W_raw,
                             const float* __restrict__ b_raw,
                             const float* __restrict__ pos_tab,
                             const float* __restrict__ type_tab,
                             const float* __restrict__ poi_tab,
                             const float* __restrict__ overlap_tab,
                             const float* __restrict__ W_comb,
                             const float* __restrict__ b_comb,
                             float* __restrict__ x,
                             unsigned char* __restrict__ zero_mask)
{
    int bl = blockIdx.x;            // b*L + l
    int l  = bl & (LL - 1);
    int s  = l >> 6;
    int v  = l & 63;
    int tid = threadIdx.x;          // 64 threads

    __shared__ float concat[80];
    const float* f = features + (size_t)bl * 3;
    float f0 = f[0], f1 = f[1], f2 = f[2];

    concat[tid] = f0 * W_raw[tid] + f1 * W_raw[64 + tid] + f2 * W_raw[128 + tid] + b_raw[tid];
    if (tid < 8) {
        int ov = overlap_tag[bl];
        concat[64 + tid] = (ov == 0) ? 0.0f : overlap_tab[ov * 8 + tid];
        int poi = poi_id[bl];
        concat[72 + tid] = (poi == 0) ? 0.0f : poi_tab[poi * 8 + tid];
    }
    if (tid == 0) zero_mask[bl] = (f0 + f1 + f2 == 0.0f) ? 1 : 0;
    __syncthreads();

    float acc = b_comb[tid];
#pragma unroll
    for (int j = 0; j < 80; j++) acc += concat[j] * W_comb[j * EE + tid];
    acc += pos_tab[s * EE + tid] + type_tab[v * EE + tid];
    x[(size_t)bl * EE + tid] = acc;
}

// ---------------- generic tiled GEMM: C[M,N] = act(A[M,K] @ W[K,N] + bias[N]) ----------------
__global__ __launch_bounds__(256) void gemm_bias(const float* __restrict__ A,
                                                 const float* __restrict__ W,
                                                 const float* __restrict__ bias,
                                                 float* __restrict__ C,
                                                 int M, int N, int K, int relu)
{
    __shared__ float As[16][64];
    __shared__ float Ws[16][64];
    int tid = threadIdx.x;
    int tx = tid & 15, ty = tid >> 4;
    int row0 = blockIdx.y * 64, col0 = blockIdx.x * 64;
    float acc[4][4] = {};

    for (int k0 = 0; k0 < K; k0 += 16) {
        for (int i = tid; i < 1024; i += 256) {
            int r = i >> 4, kk = i & 15;
            As[kk][r] = A[(size_t)(row0 + r) * K + k0 + kk];
        }
        for (int i = tid; i < 1024; i += 256) {
            int kk = i >> 6, c = i & 63;
            Ws[kk][c] = W[(size_t)(k0 + kk) * N + col0 + c];
        }
        __syncthreads();
#pragma unroll
        for (int kk = 0; kk < 16; kk++) {
            float a[4], bb[4];
#pragma unroll
            for (int i = 0; i < 4; i++) a[i] = As[kk][ty * 4 + i];
#pragma unroll
            for (int j = 0; j < 4; j++) bb[j] = Ws[kk][tx * 4 + j];
#pragma unroll
            for (int i = 0; i < 4; i++)
#pragma unroll
                for (int j = 0; j < 4; j++) acc[i][j] += a[i] * bb[j];
        }
        __syncthreads();
    }
#pragma unroll
    for (int i = 0; i < 4; i++) {
        int row = row0 + ty * 4 + i;
#pragma unroll
        for (int j = 0; j < 4; j++) {
            int col = col0 + tx * 4 + j;
            float vv = acc[i][j] + bias[col];
            if (relu) vv = fmaxf(vv, 0.0f);
            C[(size_t)row * N + col] = vv;
        }
    }
}

// ---------------- attention: structured sparse mask (same-t OR same-v), online softmax ----------------
__device__ __forceinline__ void attn_step(int k, const float* __restrict__ Ks,
                                          const float* __restrict__ Vs,
                                          const unsigned char* __restrict__ zs,
                                          const float* qv, float scale,
                                          float& m, float& ssum, float* acc)
{
    if (zs[k]) return;
    float dot = 0.0f;
#pragma unroll
    for (int d = 0; d < 8; d++) dot += qv[d] * Ks[k * 8 + d];
    dot *= scale;
    if (dot > m) {
        float c = __expf(m - dot);
        ssum *= c;
#pragma unroll
        for (int d = 0; d < 8; d++) acc[d] *= c;
        m = dot;
        ssum += 1.0f;
#pragma unroll
        for (int d = 0; d < 8; d++) acc[d] += Vs[k * 8 + d];
    } else {
        float w = __expf(dot - m);
        ssum += w;
#pragma unroll
        for (int d = 0; d < 8; d++) acc[d] += w * Vs[k * 8 + d];
    }
}

__global__ void attn_kernel(const float* __restrict__ qkv,
                            const unsigned char* __restrict__ zero_mask,
                            float* __restrict__ out)
{
    extern __shared__ float sm[];
    float* Ks = sm;                 // [1024*8]
    float* Vs = sm + 8192;          // [1024*8]
    unsigned char* zs = (unsigned char*)(sm + 16384);  // [1024]

    int b = blockIdx.x >> 3;
    int h = blockIdx.x & 7;
    int tid = threadIdx.x;          // 256 threads
    const float* base = qkv + (size_t)b * LL * 192;

    for (int i = tid; i < 8192; i += 256) {
        int l = i >> 3, d = i & 7;
        Ks[i] = base[l * 192 + 64 + h * 8 + d];
        Vs[i] = base[l * 192 + 128 + h * 8 + d];
    }
    for (int i = tid; i < 1024; i += 256) zs[i] = zero_mask[b * LL + i];
    __syncthreads();

    const float scale = 0.35355339059327373f;   // 1/sqrt(8)

    for (int q = tid; q < LL; q += 256) {
        int tq = q >> 6, vq = q & 63;
        float qv[8];
#pragma unroll
        for (int d = 0; d < 8; d++) qv[d] = base[q * 192 + h * 8 + d];

        float m = -1e30f, ssum = 0.0f;
        float acc[8] = {};

        // same-time block (64 keys, includes k==q)
        int kb = tq << 6;
        for (int j = 0; j < 64; j++)
            attn_step(kb + j, Ks, Vs, zs, qv, scale, m, ssum, acc);
        // same-type column (15 more keys)
        for (int t = 0; t < 16; t++) {
            if (t == tq) continue;
            attn_step((t << 6) + vq, Ks, Vs, zs, qv, scale, m, ssum, acc);
        }

        float inv = 1.0f / ssum;
        float* o = out + ((size_t)(b * LL + q)) * EE + h * 8;
#pragma unroll
        for (int d = 0; d < 8; d++) o[d] = acc[d] * inv;
    }
}

// ---------------- residual add + LayerNorm over E=64 ----------------
__device__ __forceinline__ float warp_sum32(float v)
{
#pragma unroll
    for (int o = 16; o > 0; o >>= 1) v += __shfl_xor_sync(0xffffffffu, v, o);
    return v;
}

__global__ void resid_ln_kernel(float* __restrict__ x,
                                const float* __restrict__ t,
                                const float* __restrict__ s,
                                const float* __restrict__ bln)
{
    int mIdx = blockIdx.x;
    int tid = threadIdx.x;          // 64 threads, 2 warps
    int lane = tid & 31, wid = tid >> 5;
    size_t off = (size_t)mIdx * EE + tid;
    float y = x[off] + t[off];

    __shared__ float r1[2], r2[2];
    float sum = warp_sum32(y);
    if (lane == 0) r1[wid] = sum;
    __syncthreads();
    float mean = (r1[0] + r1[1]) * (1.0f / 64.0f);
    float dy = y - mean;
    float sq = warp_sum32(dy * dy);
    if (lane == 0) r2[wid] = sq;
    __syncthreads();
    float var = (r2[0] + r2[1]) * (1.0f / 64.0f);
    x[off] = dy * rsqrtf(var + 1e-5f) * s[tid] + bln[tid];
}

// ---------------- head: last time-step tokens -> [B,V,3] ----------------
__global__ void head_kernel(const float* __restrict__ x,
                            const float* __restrict__ W_head,
                            const float* __restrict__ b_head,
                            float* __restrict__ out)
{
    int b = blockIdx.x;
    int tid = threadIdx.x;          // 192 threads
    int v = tid / 3, c = tid % 3;
    const float* row = x + ((size_t)(b * LL + (SS - 1) * VV + v)) * EE;
    float acc = b_head[c];
#pragma unroll
    for (int e = 0; e < EE; e++) acc += row[e] * W_head[e * 3 + c];
    out[b * (VV * 3) + tid] = acc;
}

// ---------------- launch ----------------
extern "C" void kernel_launch(void* const* d_in, const int* in_sizes, int n_in,
                              void* d_out, int out_size)
{
    const float* features    = (const float*)d_in[0];
    const int*   overlap_tag = (const int*)d_in[1];
    const int*   poi_id      = (const int*)d_in[2];
    const float* W_raw       = (const float*)d_in[3];
    const float* b_raw       = (const float*)d_in[4];
    const float* pos_tab     = (const float*)d_in[5];
    const float* type_tab    = (const float*)d_in[6];
    const float* poi_tab     = (const float*)d_in[7];
    const float* overlap_tab = (const float*)d_in[8];
    const float* W_comb      = (const float*)d_in[9];
    const float* b_comb      = (const float*)d_in[10];
    const float* Wqkv        = (const float*)d_in[11];
    const float* bqkv        = (const float*)d_in[12];
    const float* Wo          = (const float*)d_in[13];
    const float* bo          = (const float*)d_in[14];
    const float* ln1_s       = (const float*)d_in[15];
    const float* ln1_b       = (const float*)d_in[16];
    const float* W1          = (const float*)d_in[17];
    const float* b1          = (const float*)d_in[18];
    const float* W2          = (const float*)d_in[19];
    const float* b2          = (const float*)d_in[20];
    const float* ln2_s       = (const float*)d_in[21];
    const float* ln2_b       = (const float*)d_in[22];
    const float* W_head      = (const float*)d_in[23];
    const float* b_head      = (const float*)d_in[24];
    float* out = (float*)d_out;

    float *x, *qkv, *attn, *tmp, *h;
    unsigned char* zero;
    cudaGetSymbolAddress((void**)&x,    g_x);
    cudaGetSymbolAddress((void**)&qkv,  g_qkv);
    cudaGetSymbolAddress((void**)&attn, g_attn);
    cudaGetSymbolAddress((void**)&tmp,  g_tmp);
    cudaGetSymbolAddress((void**)&h,    g_h);
    cudaGetSymbolAddress((void**)&zero, g_zero);

    const int ATTN_SMEM = 16384 * 4 + 1024;   // K + V + zero flags = 66560 B
    cudaFuncSetAttribute(attn_kernel, cudaFuncAttributeMaxDynamicSharedMemorySize, ATTN_SMEM);

    embed_kernel<<<ML, 64>>>(features, overlap_tag, poi_id, W_raw, b_raw,
                             pos_tab, type_tab, poi_tab, overlap_tab,
                             W_comb, b_comb, x, zero);

    for (int l = 0; l < NL; l++) {
        // QKV: [16384,64] @ [64,192]
        gemm_bias<<<dim3(3, ML / 64), 256>>>(x, Wqkv + (size_t)l * EE * 3 * EE,
                                             bqkv + l * 3 * EE, qkv, ML, 3 * EE, EE, 0);
        // attention
        attn_kernel<<<BB * HH, 256, ATTN_SMEM>>>(qkv, zero, attn);
        // O projection: [16384,64] @ [64,64]
        gemm_bias<<<dim3(1, ML / 64), 256>>>(attn, Wo + (size_t)l * EE * EE,
                                             bo + l * EE, tmp, ML, EE, EE, 0);
        resid_ln_kernel<<<ML, 64>>>(x, tmp, ln1_s + l * EE, ln1_b + l * EE);
        // FFN1: [16384,64] @ [64,2048], relu
        gemm_bias<<<dim3(DFF / 64, ML / 64), 256>>>(x, W1 + (size_t)l * EE * DFF,
                                                    b1 + l * DFF, h, ML, DFF, EE, 1);
        // FFN2: [16384,2048] @ [2048,64]
        gemm_bias<<<dim3(1, ML / 64), 256>>>(h, W2 + (size_t)l * DFF * EE,
                                             b2 + l * EE, tmp, ML, EE, DFF, 0);
        resid_ln_kernel<<<ML, 64>>>(x, tmp, ln2_s + l * EE, ln2_b + l * EE);
    }

    head_kernel<<<BB, VV * 3>>>(x, W_head, b_head, out);
}

// round 2
// speedup vs baseline: 1.9553x; 1.9553x over previous
#include <cuda_runtime.h>
#include <cuda_bf16.h>
#include <math.h>

// Problem constants
#define BB 16
#define SS 16
#define VV 64
#define EE 64
#define HH 8
#define NL 4
#define DFF 2048
#define LL 1024
#define DH 8
#define ML (BB*LL)

// ---------------- scratch ----------------
__device__ float g_x[ML * EE];
__device__ float g_qkv[ML * 3 * EE];
__device__ float g_attn[ML * EE];
__device__ unsigned char g_zero[ML];

// ---------------- helpers ----------------
__device__ __forceinline__ unsigned pack_bf16(__nv_bfloat16 a, __nv_bfloat16 b) {
    unsigned short ua = *(unsigned short*)&a, ub = *(unsigned short*)&b;
    return (unsigned)ua | ((unsigned)ub << 16);
}

__device__ __forceinline__ void split2(float v, __nv_bfloat16& hi, __nv_bfloat16& lo) {
    hi = __float2bfloat16(v);
    lo = __float2bfloat16(v - __bfloat162float(hi));
}

// pack two floats into hi-pair and lo-pair
__device__ __forceinline__ void split_pair(float v0, float v1, unsigned& hp, unsigned& lp) {
    __nv_bfloat16 h0, l0, h1, l1;
    split2(v0, h0, l0);
    split2(v1, h1, l1);
    hp = pack_bf16(h0, h1);
    lp = pack_bf16(l0, l1);
}

__device__ __forceinline__ void mma_bf16(float* c, const unsigned* a, const unsigned* b) {
    asm volatile(
        "mma.sync.aligned.m16n8k16.row.col.f32.bf16.bf16.f32 "
        "{%0,%1,%2,%3}, {%4,%5,%6,%7}, {%8,%9}, {%0,%1,%2,%3};\n"
        : "+f"(c[0]), "+f"(c[1]), "+f"(c[2]), "+f"(c[3])
        : "r"(a[0]), "r"(a[1]), "r"(a[2]), "r"(a[3]), "r"(b[0]), "r"(b[1]));
}

__device__ __forceinline__ float warp_sum32(float v) {
#pragma unroll
    for (int o = 16; o > 0; o >>= 1) v += __shfl_xor_sync(0xffffffffu, v, o);
    return v;
}

// ---------------- embed ----------------
__global__ void embed_kernel(const float* __restrict__ features,
                             const int* __restrict__ overlap_tag,
                             const int* __restrict__ poi_id,
                             const float* __restrict__ W_raw,
                             const float* __restrict__ b_raw,
                             const float* __restrict__ pos_tab,
                             const float* __restrict__ type_tab,
                             const float* __restrict__ poi_tab,
                             const float* __restrict__ overlap_tab,
                             const float* __restrict__ W_comb,
                             const float* __restrict__ b_comb,
                             float* __restrict__ x,
                             unsigned char* __restrict__ zero_mask)
{
    int bl = blockIdx.x;
    int l  = bl & (LL - 1);
    int s  = l >> 6;
    int v  = l & 63;
    int tid = threadIdx.x;  // 64

    __shared__ float concat[80];
    const float* f = features + (size_t)bl * 3;
    float f0 = f[0], f1 = f[1], f2 = f[2];

    concat[tid] = f0 * W_raw[tid] + f1 * W_raw[64 + tid] + f2 * W_raw[128 + tid] + b_raw[tid];
    if (tid < 8) {
        int ov = overlap_tag[bl];
        concat[64 + tid] = (ov == 0) ? 0.0f : overlap_tab[ov * 8 + tid];
        int poi = poi_id[bl];
        concat[72 + tid] = (poi == 0) ? 0.0f : poi_tab[poi * 8 + tid];
    }
    if (tid == 0) zero_mask[bl] = (f0 + f1 + f2 == 0.0f) ? 1 : 0;
    __syncthreads();

    float acc = b_comb[tid];
#pragma unroll
    for (int j = 0; j < 80; j++) acc += concat[j] * W_comb[j * EE + tid];
    acc += pos_tab[s * EE + tid] + type_tab[v * EE + tid];
    x[(size_t)bl * EE + tid] = acc;
}

// ---------------- generic split-bf16 GEMM: C = A[M,K]@W[K,N] + bias ----------------
// BM=128, BN=64, BK=32. 256 threads = 8 warps (4m x 2n), warp tile 32x32.
__global__ __launch_bounds__(256) void gemm_split(const float* __restrict__ A,
                                                  const float* __restrict__ W,
                                                  const float* __restrict__ bias,
                                                  float* __restrict__ C,
                                                  int N, int K)
{
    __shared__ __align__(16) __nv_bfloat16 Ah[128 * 34];
    __shared__ __align__(16) __nv_bfloat16 Al[128 * 34];
    __shared__ __align__(16) __nv_bfloat16 Wh[64 * 34];
    __shared__ __align__(16) __nv_bfloat16 Wl[64 * 34];

    int tid = threadIdx.x;
    int w = tid >> 5, lane = tid & 31;
    int wm = w >> 1, wn = w & 1;
    int rm = wm * 32, cn = wn * 32;
    int row0 = blockIdx.y * 128, col0 = blockIdx.x * 64;
    int gr = lane >> 2, gc = (lane & 3) * 2;

    float acc[2][4][4];
#pragma unroll
    for (int i = 0; i < 2; i++)
#pragma unroll
        for (int j = 0; j < 4; j++)
#pragma unroll
            for (int r = 0; r < 4; r++) acc[i][j][r] = 0.0f;

    for (int k0 = 0; k0 < K; k0 += 32) {
        // load A tile 128x32 (1024 float4)
        for (int i = tid; i < 1024; i += 256) {
            int r = i >> 3, f4 = i & 7;
            float4 v = *(const float4*)&A[(size_t)(row0 + r) * K + k0 + f4 * 4];
            unsigned hp, lp;
            split_pair(v.x, v.y, hp, lp);
            *(unsigned*)&Ah[r * 34 + f4 * 4] = hp;
            *(unsigned*)&Al[r * 34 + f4 * 4] = lp;
            split_pair(v.z, v.w, hp, lp);
            *(unsigned*)&Ah[r * 34 + f4 * 4 + 2] = hp;
            *(unsigned*)&Al[r * 34 + f4 * 4 + 2] = lp;
        }
        // load W tile 32x64 transposed to [n][k] (512 float4)
        for (int i = tid; i < 512; i += 256) {
            int kr = i >> 4, f4 = i & 15;
            float4 v = *(const float4*)&W[(size_t)(k0 + kr) * N + col0 + f4 * 4];
            __nv_bfloat16 h, lo;
            split2(v.x, h, lo); Wh[(f4 * 4 + 0) * 34 + kr] = h; Wl[(f4 * 4 + 0) * 34 + kr] = lo;
            split2(v.y, h, lo); Wh[(f4 * 4 + 1) * 34 + kr] = h; Wl[(f4 * 4 + 1) * 34 + kr] = lo;
            split2(v.z, h, lo); Wh[(f4 * 4 + 2) * 34 + kr] = h; Wl[(f4 * 4 + 2) * 34 + kr] = lo;
            split2(v.w, h, lo); Wh[(f4 * 4 + 3) * 34 + kr] = h; Wl[(f4 * 4 + 3) * 34 + kr] = lo;
        }
        __syncthreads();

#pragma unroll
        for (int kt = 0; kt < 2; kt++) {
            int kk = kt * 16;
            unsigned ah[2][4], al[2][4], bh[4][2], bl[4][2];
#pragma unroll
            for (int mi = 0; mi < 2; mi++) {
                int r = rm + mi * 16;
                ah[mi][0] = *(unsigned*)&Ah[(r + gr) * 34 + kk + gc];
                ah[mi][1] = *(unsigned*)&Ah[(r + gr + 8) * 34 + kk + gc];
                ah[mi][2] = *(unsigned*)&Ah[(r + gr) * 34 + kk + gc + 8];
                ah[mi][3] = *(unsigned*)&Ah[(r + gr + 8) * 34 + kk + gc + 8];
                al[mi][0] = *(unsigned*)&Al[(r + gr) * 34 + kk + gc];
                al[mi][1] = *(unsigned*)&Al[(r + gr + 8) * 34 + kk + gc];
                al[mi][2] = *(unsigned*)&Al[(r + gr) * 34 + kk + gc + 8];
                al[mi][3] = *(unsigned*)&Al[(r + gr + 8) * 34 + kk + gc + 8];
            }
#pragma unroll
            for (int ni = 0; ni < 4; ni++) {
                int n = cn + ni * 8 + gr;
                bh[ni][0] = *(unsigned*)&Wh[n * 34 + kk + gc];
                bh[ni][1] = *(unsigned*)&Wh[n * 34 + kk + gc + 8];
                bl[ni][0] = *(unsigned*)&Wl[n * 34 + kk + gc];
                bl[ni][1] = *(unsigned*)&Wl[n * 34 + kk + gc + 8];
            }
#pragma unroll
            for (int mi = 0; mi < 2; mi++)
#pragma unroll
                for (int ni = 0; ni < 4; ni++) {
                    mma_bf16(acc[mi][ni], ah[mi], bh[ni]);
                    mma_bf16(acc[mi][ni], al[mi], bh[ni]);
                    mma_bf16(acc[mi][ni], ah[mi], bl[ni]);
                }
        }
        __syncthreads();
    }

#pragma unroll
    for (int mi = 0; mi < 2; mi++) {
        int r0 = row0 + rm + mi * 16 + gr;
#pragma unroll
        for (int ni = 0; ni < 4; ni++) {
            int c = col0 + cn + ni * 8 + gc;
            float b0 = bias[c], b1 = bias[c + 1];
            float2 v0 = make_float2(acc[mi][ni][0] + b0, acc[mi][ni][1] + b1);
            float2 v1 = make_float2(acc[mi][ni][2] + b0, acc[mi][ni][3] + b1);
            *(float2*)&C[(size_t)r0 * N + c] = v0;
            *(float2*)&C[(size_t)(r0 + 8) * N + c] = v1;
        }
    }
}

// ---------------- Wo projection + residual + LN1 (BM=64, N=64, K=64) ----------------
__global__ __launch_bounds__(256) void gemm_wo_ln(const float* __restrict__ A,
                                                  const float* __restrict__ W,
                                                  const float* __restrict__ bias,
                                                  float* __restrict__ x,
                                                  const float* __restrict__ ln_s,
                                                  const float* __restrict__ ln_b)
{
    __shared__ __align__(16) __nv_bfloat16 Ah[64 * 34];
    __shared__ __align__(16) __nv_bfloat16 Al[64 * 34];
    __shared__ __align__(16) __nv_bfloat16 Wh[64 * 34];
    __shared__ __align__(16) __nv_bfloat16 Wl[64 * 34];
    __shared__ float buf[64 * 65];

    int tid = threadIdx.x;
    int w = tid >> 5, lane = tid & 31;
    int wm = w >> 1, wn = w & 1;
    int rm = wm * 16, cn = wn * 32;
    int row0 = blockIdx.x * 64;
    int gr = lane >> 2, gc = (lane & 3) * 2;

    float acc[4][4];
#pragma unroll
    for (int j = 0; j < 4; j++)
#pragma unroll
        for (int r = 0; r < 4; r++) acc[j][r] = 0.0f;

    for (int k0 = 0; k0 < 64; k0 += 32) {
        for (int i = tid; i < 512; i += 256) {
            int r = i >> 3, f4 = i & 7;
            float4 v = *(const float4*)&A[(size_t)(row0 + r) * 64 + k0 + f4 * 4];
            unsigned hp, lp;
            split_pair(v.x, v.y, hp, lp);
            *(unsigned*)&Ah[r * 34 + f4 * 4] = hp;
            *(unsigned*)&Al[r * 34 + f4 * 4] = lp;
            split_pair(v.z, v.w, hp, lp);
            *(unsigned*)&Ah[r * 34 + f4 * 4 + 2] = hp;
            *(unsigned*)&Al[r * 34 + f4 * 4 + 2] = lp;
        }
        for (int i = tid; i < 512; i += 256) {
            int kr = i >> 4, f4 = i & 15;
            float4 v = *(const float4*)&W[(size_t)(k0 + kr) * 64 + f4 * 4];
            __nv_bfloat16 h, lo;
            split2(v.x, h, lo); Wh[(f4 * 4 + 0) * 34 + kr] = h; Wl[(f4 * 4 + 0) * 34 + kr] = lo;
            split2(v.y, h, lo); Wh[(f4 * 4 + 1) * 34 + kr] = h; Wl[(f4 * 4 + 1) * 34 + kr] = lo;
            split2(v.z, h, lo); Wh[(f4 * 4 + 2) * 34 + kr] = h; Wl[(f4 * 4 + 2) * 34 + kr] = lo;
            split2(v.w, h, lo); Wh[(f4 * 4 + 3) * 34 + kr] = h; Wl[(f4 * 4 + 3) * 34 + kr] = lo;
        }
        __syncthreads();

#pragma unroll
        for (int kt = 0; kt < 2; kt++) {
            int kk = kt * 16;
            unsigned ah[4], al[4], bh[4][2], bl[4][2];
            ah[0] = *(unsigned*)&Ah[(rm + gr) * 34 + kk + gc];
            ah[1] = *(unsigned*)&Ah[(rm + gr + 8) * 34 + kk + gc];
            ah[2] = *(unsigned*)&Ah[(rm + gr) * 34 + kk + gc + 8];
            ah[3] = *(unsigned*)&Ah[(rm + gr + 8) * 34 + kk + gc + 8];
            al[0] = *(unsigned*)&Al[(rm + gr) * 34 + kk + gc];
            al[1] = *(unsigned*)&Al[(rm + gr + 8) * 34 + kk + gc];
            al[2] = *(unsigned*)&Al[(rm + gr) * 34 + kk + gc + 8];
            al[3] = *(unsigned*)&Al[(rm + gr + 8) * 34 + kk + gc + 8];
#pragma unroll
            for (int ni = 0; ni < 4; ni++) {
                int n = cn + ni * 8 + gr;
                bh[ni][0] = *(unsigned*)&Wh[n * 34 + kk + gc];
                bh[ni][1] = *(unsigned*)&Wh[n * 34 + kk + gc + 8];
                bl[ni][0] = *(unsigned*)&Wl[n * 34 + kk + gc];
                bl[ni][1] = *(unsigned*)&Wl[n * 34 + kk + gc + 8];
            }
#pragma unroll
            for (int ni = 0; ni < 4; ni++) {
                mma_bf16(acc[ni], ah, bh[ni]);
                mma_bf16(acc[ni], al, bh[ni]);
                mma_bf16(acc[ni], ah, bl[ni]);
            }
        }
        __syncthreads();
    }

#pragma unroll
    for (int ni = 0; ni < 4; ni++) {
        int c = cn + ni * 8 + gc;
        float b0 = bias[c], b1 = bias[c + 1];
        buf[(rm + gr) * 65 + c] = acc[ni][0] + b0;
        buf[(rm + gr) * 65 + c + 1] = acc[ni][1] + b1;
        buf[(rm + gr + 8) * 65 + c] = acc[ni][2] + b0;
        buf[(rm + gr + 8) * 65 + c + 1] = acc[ni][3] + b1;
    }
    __syncthreads();

    // LN over each row (8 rows per warp)
    for (int rr = 0; rr < 8; rr++) {
        int row = w * 8 + rr;
        size_t go = (size_t)(row0 + row) * 64;
        float y0 = buf[row * 65 + lane] + x[go + lane];
        float y1 = buf[row * 65 + lane + 32] + x[go + lane + 32];
        float mean = warp_sum32(y0 + y1) * (1.0f / 64.0f);
        float d0 = y0 - mean, d1 = y1 - mean;
        float var = warp_sum32(d0 * d0 + d1 * d1) * (1.0f / 64.0f);
        float inv = rsqrtf(var + 1e-5f);
        x[go + lane] = d0 * inv * ln_s[lane] + ln_b[lane];
        x[go + lane + 32] = d1 * inv * ln_s[lane + 32] + ln_b[lane + 32];
    }
}

// ---------------- fused FFN: relu(x@W1+b1)@W2+b2 + residual + LN2 ----------------
// BM=64 rows/block, DFF in 32 chunks of 64. 256 threads = 8 warps (4m x 2n), warp tile 16x32.
__global__ __launch_bounds__(256) void ffn_fused(const float* __restrict__ xin,
                                                 const float* __restrict__ W1,
                                                 const float* __restrict__ b1,
                                                 const float* __restrict__ W2,
                                                 const float* __restrict__ b2,
                                                 float* __restrict__ x,
                                                 const float* __restrict__ ln_s,
                                                 const float* __restrict__ ln_b)
{
    extern __shared__ __align__(16) char smem[];
    __nv_bfloat16* Xh  = (__nv_bfloat16*)(smem);
    __nv_bfloat16* Xl  = (__nv_bfloat16*)(smem + 8448);
    __nv_bfloat16* W1h = (__nv_bfloat16*)(smem + 16896);
    __nv_bfloat16* W1l = (__nv_bfloat16*)(smem + 25344);
    __nv_bfloat16* W2h = (__nv_bfloat16*)(smem + 33792);
    __nv_bfloat16* W2l = (__nv_bfloat16*)(smem + 42240);
    __nv_bfloat16* Hh  = (__nv_bfloat16*)(smem + 50688);
    __nv_bfloat16* Hl  = (__nv_bfloat16*)(smem + 59136);
    float* buf = (float*)(smem + 16896);   // aliases W1h/W1l, used after chunk loop

    int tid = threadIdx.x;
    int w = tid >> 5, lane = tid & 31;
    int wm = w >> 1, wn = w & 1;
    int rm = wm * 16, cn = wn * 32;
    int row0 = blockIdx.x * 64;
    int gr = lane >> 2, gc = (lane & 3) * 2;

    // load x tile 64x64, split
    for (int i = tid; i < 1024; i += 256) {
        int r = i >> 4, f4 = i & 15;
        float4 v = *(const float4*)&xin[(size_t)(row0 + r) * 64 + f4 * 4];
        unsigned hp, lp;
        split_pair(v.x, v.y, hp, lp);
        *(unsigned*)&Xh[r * 66 + f4 * 4] = hp;
        *(unsigned*)&Xl[r * 66 + f4 * 4] = lp;
        split_pair(v.z, v.w, hp, lp);
        *(unsigned*)&Xh[r * 66 + f4 * 4 + 2] = hp;
        *(unsigned*)&Xl[r * 66 + f4 * 4 + 2] = lp;
    }

    float acc2[4][4];
#pragma unroll
    for (int j = 0; j < 4; j++)
#pragma unroll
        for (int r = 0; r < 4; r++) acc2[j][r] = 0.0f;

    for (int c = 0; c < 32; c++) {
        // load W1 chunk (64k x 64n) and W2 chunk (64k x 64n), transposed to [n][k]
        for (int i = tid; i < 1024; i += 256) {
            int kr = i >> 4, f4 = i & 15;
            float4 v = *(const float4*)&W1[(size_t)kr * DFF + c * 64 + f4 * 4];
            __nv_bfloat16 h, lo;
            split2(v.x, h, lo); W1h[(f4 * 4 + 0) * 66 + kr] = h; W1l[(f4 * 4 + 0) * 66 + kr] = lo;
            split2(v.y, h, lo); W1h[(f4 * 4 + 1) * 66 + kr] = h; W1l[(f4 * 4 + 1) * 66 + kr] = lo;
            split2(v.z, h, lo); W1h[(f4 * 4 + 2) * 66 + kr] = h; W1l[(f4 * 4 + 2) * 66 + kr] = lo;
            split2(v.w, h, lo); W1h[(f4 * 4 + 3) * 66 + kr] = h; W1l[(f4 * 4 + 3) * 66 + kr] = lo;
        }
        for (int i = tid; i < 1024; i += 256) {
            int kr = i >> 4, f4 = i & 15;
            float4 v = *(const float4*)&W2[(size_t)(c * 64 + kr) * 64 + f4 * 4];
            __nv_bfloat16 h, lo;
            split2(v.x, h, lo); W2h[(f4 * 4 + 0) * 66 + kr] = h; W2l[(f4 * 4 + 0) * 66 + kr] = lo;
            split2(v.y, h, lo); W2h[(f4 * 4 + 1) * 66 + kr] = h; W2l[(f4 * 4 + 1) * 66 + kr] = lo;
            split2(v.z, h, lo); W2h[(f4 * 4 + 2) * 66 + kr] = h; W2l[(f4 * 4 + 2) * 66 + kr] = lo;
            split2(v.w, h, lo); W2h[(f4 * 4 + 3) * 66 + kr] = h; W2l[(f4 * 4 + 3) * 66 + kr] = lo;
        }
        __syncthreads();

        // GEMM1: h = relu(x @ W1c + b1c), warp tile 16x32
        float hacc[4][4];
#pragma unroll
        for (int j = 0; j < 4; j++)
#pragma unroll
            for (int r = 0; r < 4; r++) hacc[j][r] = 0.0f;

#pragma unroll
        for (int kt = 0; kt < 4; kt++) {
            int kk = kt * 16;
            unsigned ah[4], al[4], bh[4][2], bl[4][2];
            ah[0] = *(unsigned*)&Xh[(rm + gr) * 66 + kk + gc];
            ah[1] = *(unsigned*)&Xh[(rm + gr + 8) * 66 + kk + gc];
            ah[2] = *(unsigned*)&Xh[(rm + gr) * 66 + kk + gc + 8];
            ah[3] = *(unsigned*)&Xh[(rm + gr + 8) * 66 + kk + gc + 8];
            al[0] = *(unsigned*)&Xl[(rm + gr) * 66 + kk + gc];
            al[1] = *(unsigned*)&Xl[(rm + gr + 8) * 66 + kk + gc];
            al[2] = *(unsigned*)&Xl[(rm + gr) * 66 + kk + gc + 8];
            al[3] = *(unsigned*)&Xl[(rm + gr + 8) * 66 + kk + gc + 8];
#pragma unroll
            for (int ni = 0; ni < 4; ni++) {
                int n = cn + ni * 8 + gr;
                bh[ni][0] = *(unsigned*)&W1h[n * 66 + kk + gc];
                bh[ni][1] = *(unsigned*)&W1h[n * 66 + kk + gc + 8];
                bl[ni][0] = *(unsigned*)&W1l[n * 66 + kk + gc];
                bl[ni][1] = *(unsigned*)&W1l[n * 66 + kk + gc + 8];
            }
#pragma unroll
            for (int ni = 0; ni < 4; ni++) {
                mma_bf16(hacc[ni], ah, bh[ni]);
                mma_bf16(hacc[ni], al, bh[ni]);
                mma_bf16(hacc[ni], ah, bl[ni]);
            }
        }

        // bias + relu + split-store h to smem [row][k_local]
#pragma unroll
        for (int ni = 0; ni < 4; ni++) {
            int cl = cn + ni * 8 + gc;        // local col 0..63
            int cg = c * 64 + cl;             // global DFF col
            float v0 = fmaxf(hacc[ni][0] + b1[cg], 0.0f);
            float v1 = fmaxf(hacc[ni][1] + b1[cg + 1], 0.0f);
            float v2 = fmaxf(hacc[ni][2] + b1[cg], 0.0f);
            float v3 = fmaxf(hacc[ni][3] + b1[cg + 1], 0.0f);
            unsigned hp, lp;
            split_pair(v0, v1, hp, lp);
            *(unsigned*)&Hh[(rm + gr) * 66 + cl] = hp;
            *(unsigned*)&Hl[(rm + gr) * 66 + cl] = lp;
            split_pair(v2, v3, hp, lp);
            *(unsigned*)&Hh[(rm + gr + 8) * 66 + cl] = hp;
            *(unsigned*)&Hl[(rm + gr + 8) * 66 + cl] = lp;
        }
        __syncthreads();

        // GEMM2: acc2 += h @ W2c
#pragma unroll
        for (int kt = 0; kt < 4; kt++) {
            int kk = kt * 16;
            unsigned ah[4], al[4], bh[4][2], bl[4][2];
            ah[0] = *(unsigned*)&Hh[(rm + gr) * 66 + kk + gc];
            ah[1] = *(unsigned*)&Hh[(rm + gr + 8) * 66 + kk + gc];
            ah[2] = *(unsigned*)&Hh[(rm + gr) * 66 + kk + gc + 8];
            ah[3] = *(unsigned*)&Hh[(rm + gr + 8) * 66 + kk + gc + 8];
            al[0] = *(unsigned*)&Hl[(rm + gr) * 66 + kk + gc];
            al[1] = *(unsigned*)&Hl[(rm + gr + 8) * 66 + kk + gc];
            al[2] = *(unsigned*)&Hl[(rm + gr) * 66 + kk + gc + 8];
            al[3] = *(unsigned*)&Hl[(rm + gr + 8) * 66 + kk + gc + 8];
#pragma unroll
            for (int ni = 0; ni < 4; ni++) {
                int n = cn + ni * 8 + gr;
                bh[ni][0] = *(unsigned*)&W2h[n * 66 + kk + gc];
                bh[ni][1] = *(unsigned*)&W2h[n * 66 + kk + gc + 8];
                bl[ni][0] = *(unsigned*)&W2l[n * 66 + kk + gc];
                bl[ni][1] = *(unsigned*)&W2l[n * 66 + kk + gc + 8];
            }
#pragma unroll
            for (int ni = 0; ni < 4; ni++) {
                mma_bf16(acc2[ni], ah, bh[ni]);
                mma_bf16(acc2[ni], al, bh[ni]);
                mma_bf16(acc2[ni], ah, bl[ni]);
            }
        }
        __syncthreads();   // protect W1s/W2s/Hs before next chunk
    }

    // epilogue: + b2 -> buf, + residual, LN2
#pragma unroll
    for (int ni = 0; ni < 4; ni++) {
        int cc = cn + ni * 8 + gc;
        float b0 = b2[cc], b1v = b2[cc + 1];
        buf[(rm + gr) * 65 + cc] = acc2[ni][0] + b0;
        buf[(rm + gr) * 65 + cc + 1] = acc2[ni][1] + b1v;
        buf[(rm + gr + 8) * 65 + cc] = acc2[ni][2] + b0;
        buf[(rm + gr + 8) * 65 + cc + 1] = acc2[ni][3] + b1v;
    }
    __syncthreads();

    for (int rr = 0; rr < 8; rr++) {
        int row = w * 8 + rr;
        size_t go = (size_t)(row0 + row) * 64;
        float y0 = buf[row * 65 + lane] + xin[go + lane];
        float y1 = buf[row * 65 + lane + 32] + xin[go + lane + 32];
        float mean = warp_sum32(y0 + y1) * (1.0f / 64.0f);
        float d0 = y0 - mean, d1 = y1 - mean;
        float var = warp_sum32(d0 * d0 + d1 * d1) * (1.0f / 64.0f);
        float inv = rsqrtf(var + 1e-5f);
        x[go + lane] = d0 * inv * ln_s[lane] + ln_b[lane];
        x[go + lane + 32] = d1 * inv * ln_s[lane + 32] + ln_b[lane + 32];
    }
}

// ---------------- attention (structured sparse) ----------------
__device__ __forceinline__ void attn_step(int k, const float* __restrict__ Ks,
                                          const float* __restrict__ Vs,
                                          const unsigned char* __restrict__ zs,
                                          const float* qv, float scale,
                                          float& m, float& ssum, float* acc)
{
    if (zs[k]) return;
    float dot = 0.0f;
#pragma unroll
    for (int d = 0; d < 8; d++) dot += qv[d] * Ks[k * 8 + d];
    dot *= scale;
    if (dot > m) {
        float cc = __expf(m - dot);
        ssum *= cc;
#pragma unroll
        for (int d = 0; d < 8; d++) acc[d] *= cc;
        m = dot;
        ssum += 1.0f;
#pragma unroll
        for (int d = 0; d < 8; d++) acc[d] += Vs[k * 8 + d];
    } else {
        float wgt = __expf(dot - m);
        ssum += wgt;
#pragma unroll
        for (int d = 0; d < 8; d++) acc[d] += wgt * Vs[k * 8 + d];
    }
}

__global__ void attn_kernel(const float* __restrict__ qkv,
                            const unsigned char* __restrict__ zero_mask,
                            float* __restrict__ out)
{
    extern __shared__ float sm[];
    float* Ks = sm;
    float* Vs = sm + 8192;
    unsigned char* zs = (unsigned char*)(sm + 16384);

    int b = blockIdx.x >> 3;
    int h = blockIdx.x & 7;
    int tid = threadIdx.x;  // 512
    const float* base = qkv + (size_t)b * LL * 192;

    for (int i = tid; i < 8192; i += 512) {
        int l = i >> 3, d = i & 7;
        Ks[i] = base[l * 192 + 64 + h * 8 + d];
        Vs[i] = base[l * 192 + 128 + h * 8 + d];
    }
    for (int i = tid; i < 1024; i += 512) zs[i] = zero_mask[b * LL + i];
    __syncthreads();

    const float scale = 0.35355339059327373f;

    for (int q = tid; q < LL; q += 512) {
        int tq = q >> 6, vq = q & 63;
        float qv[8];
#pragma unroll
        for (int d = 0; d < 8; d++) qv[d] = base[q * 192 + h * 8 + d];

        float m = -1e30f, ssum = 0.0f;
        float acc[8] = {};

        int kb = tq << 6;
        for (int j = 0; j < 64; j++)
            attn_step(kb + j, Ks, Vs, zs, qv, scale, m, ssum, acc);
        for (int t = 0; t < 16; t++) {
            if (t == tq) continue;
            attn_step((t << 6) + vq, Ks, Vs, zs, qv, scale, m, ssum, acc);
        }

        float inv = 1.0f / ssum;
        float* o = out + ((size_t)(b * LL + q)) * EE + h * 8;
#pragma unroll
        for (int d = 0; d < 8; d++) o[d] = acc[d] * inv;
    }
}

// ---------------- head ----------------
__global__ void head_kernel(const float* __restrict__ x,
                            const float* __restrict__ W_head,
                            const float* __restrict__ b_head,
                            float* __restrict__ out)
{
    int b = blockIdx.x;
    int tid = threadIdx.x;  // 192
    int v = tid / 3, c = tid % 3;
    const float* row = x + ((size_t)(b * LL + (SS - 1) * VV + v)) * EE;
    float acc = b_head[c];
#pragma unroll
    for (int e = 0; e < EE; e++) acc += row[e] * W_head[e * 3 + c];
    out[b * (VV * 3) + tid] = acc;
}

// ---------------- launch ----------------
extern "C" void kernel_launch(void* const* d_in, const int* in_sizes, int n_in,
                              void* d_out, int out_size)
{
    const float* features    = (const float*)d_in[0];
    const int*   overlap_tag = (const int*)d_in[1];
    const int*   poi_id      = (const int*)d_in[2];
    const float* W_raw       = (const float*)d_in[3];
    const float* b_raw       = (const float*)d_in[4];
    const float* pos_tab     = (const float*)d_in[5];
    const float* type_tab    = (const float*)d_in[6];
    const float* poi_tab     = (const float*)d_in[7];
    const float* overlap_tab = (const float*)d_in[8];
    const float* W_comb      = (const float*)d_in[9];
    const float* b_comb      = (const float*)d_in[10];
    const float* Wqkv        = (const float*)d_in[11];
    const float* bqkv        = (const float*)d_in[12];
    const float* Wo          = (const float*)d_in[13];
    const float* bo          = (const float*)d_in[14];
    const float* ln1_s       = (const float*)d_in[15];
    const float* ln1_b       = (const float*)d_in[16];
    const float* W1          = (const float*)d_in[17];
    const float* b1          = (const float*)d_in[18];
    const float* W2          = (const float*)d_in[19];
    const float* b2          = (const float*)d_in[20];
    const float* ln2_s       = (const float*)d_in[21];
    const float* ln2_b       = (const float*)d_in[22];
    const float* W_head      = (const float*)d_in[23];
    const float* b_head      = (const float*)d_in[24];
    float* out = (float*)d_out;

    float *x, *qkv, *attn;
    unsigned char* zero;
    cudaGetSymbolAddress((void**)&x,    g_x);
    cudaGetSymbolAddress((void**)&qkv,  g_qkv);
    cudaGetSymbolAddress((void**)&attn, g_attn);
    cudaGetSymbolAddress((void**)&zero, g_zero);

    const int ATTN_SMEM = 16384 * 4 + 1024;
    const int FFN_SMEM  = 67584;
    cudaFuncSetAttribute(attn_kernel, cudaFuncAttributeMaxDynamicSharedMemorySize, ATTN_SMEM);
    cudaFuncSetAttribute(ffn_fused, cudaFuncAttributeMaxDynamicSharedMemorySize, FFN_SMEM);

    embed_kernel<<<ML, 64>>>(features, overlap_tag, poi_id, W_raw, b_raw,
                             pos_tab, type_tab, poi_tab, overlap_tab,
                             W_comb, b_comb, x, zero);

    for (int l = 0; l < NL; l++) {
        gemm_split<<<dim3(3, ML / 128), 256>>>(x, Wqkv + (size_t)l * EE * 3 * EE,
                                               bqkv + l * 3 * EE, qkv, 3 * EE, EE);
        attn_kernel<<<BB * HH, 512, ATTN_SMEM>>>(qkv, zero, attn);
        gemm_wo_ln<<<ML / 64, 256>>>(attn, Wo + (size_t)l * EE * EE, bo + l * EE,
                                     x, ln1_s + l * EE, ln1_b + l * EE);
        ffn_fused<<<ML / 64, 256, FFN_SMEM>>>(x, W1 + (size_t)l * EE * DFF, b1 + l * DFF,
                                              W2 + (size_t)l * DFF * EE, b2 + l * EE,
                                              x, ln2_s + l * EE, ln2_b + l * EE);
    }

    head_kernel<<<BB, VV * 3>>>(x, W_head, b_head, out);
}

// round 3
// speedup vs baseline: 4.5387x; 2.3212x over previous
#include <cuda_runtime.h>
#include <cuda_bf16.h>
#include <math.h>

#define BB 16
#define SS 16
#define VV 64
#define EE 64
#define HH 8
#define NL 4
#define DFF 2048
#define LL 1024
#define ML (BB*LL)
#define SP 72   // smem row stride (bf16 elements)

// ---------------- scratch ----------------
__device__ float g_x[ML * EE];
__device__ float g_q[ML * EE];
__device__ float g_k[ML * EE];
__device__ float g_v[ML * EE];
__device__ float g_attn[ML * EE];
__device__ unsigned char g_zero[ML];

// pre-split transposed weights ([n][k] layout, bf16 hi/lo)
__device__ __align__(256) __nv_bfloat16 g_qkvT_h[NL * 192 * 64];
__device__ __align__(256) __nv_bfloat16 g_qkvT_l[NL * 192 * 64];
__device__ __align__(256) __nv_bfloat16 g_woT_h[NL * 64 * 64];
__device__ __align__(256) __nv_bfloat16 g_woT_l[NL * 64 * 64];
__device__ __align__(256) __nv_bfloat16 g_w1T_h[NL * DFF * 64];
__device__ __align__(256) __nv_bfloat16 g_w1T_l[NL * DFF * 64];
__device__ __align__(256) __nv_bfloat16 g_w2T_h[NL * DFF * 64];
__device__ __align__(256) __nv_bfloat16 g_w2T_l[NL * DFF * 64];

// ---------------- helpers ----------------
__device__ __forceinline__ unsigned pack_bf16(__nv_bfloat16 a, __nv_bfloat16 b) {
    unsigned short ua = *(unsigned short*)&a, ub = *(unsigned short*)&b;
    return (unsigned)ua | ((unsigned)ub << 16);
}
__device__ __forceinline__ void split2(float v, __nv_bfloat16& hi, __nv_bfloat16& lo) {
    hi = __float2bfloat16(v);
    lo = __float2bfloat16(v - __bfloat162float(hi));
}
__device__ __forceinline__ void split_pair(float v0, float v1, unsigned& hp, unsigned& lp) {
    __nv_bfloat16 h0, l0, h1, l1;
    split2(v0, h0, l0);
    split2(v1, h1, l1);
    hp = pack_bf16(h0, h1);
    lp = pack_bf16(l0, l1);
}
__device__ __forceinline__ void mma_bf16(float* c, const unsigned* a, const unsigned* b) {
    asm volatile(
        "mma.sync.aligned.m16n8k16.row.col.f32.bf16.bf16.f32 "
        "{%0,%1,%2,%3}, {%4,%5,%6,%7}, {%8,%9}, {%0,%1,%2,%3};\n"
        : "+f"(c[0]), "+f"(c[1]), "+f"(c[2]), "+f"(c[3])
        : "r"(a[0]), "r"(a[1]), "r"(a[2]), "r"(a[3]), "r"(b[0]), "r"(b[1]));
}
__device__ __forceinline__ float warp_sum32(float v) {
#pragma unroll
    for (int o = 16; o > 0; o >>= 1) v += __shfl_xor_sync(0xffffffffu, v, o);
    return v;
}

#define CP_ASYNC16(dst, src) \
    asm volatile("cp.async.ca.shared.global [%0], [%1], 16;\n" :: "r"(dst), "l"(src))
#define CP_COMMIT() asm volatile("cp.async.commit_group;\n")
#define CP_WAIT1()  asm volatile("cp.async.wait_group 1;\n")

// ---------------- weight prep: split + transpose ----------------
__global__ void prep_weights(const float* __restrict__ Wqkv,
                             const float* __restrict__ Wo,
                             const float* __restrict__ W1,
                             const float* __restrict__ W2)
{
    int t = blockIdx.x * 256 + threadIdx.x;
    int which = blockIdx.y;
    if (which == 0) {                       // qkv: [64k][192n] -> [n][k]
        if (t >= NL * 12288) return;
        int layer = t / 12288, rem = t % 12288, n = rem >> 6, k = rem & 63;
        float v = Wqkv[(size_t)layer * 12288 + k * 192 + n];
        split2(v, g_qkvT_h[t], g_qkvT_l[t]);
    } else if (which == 1) {                // wo: [64k][64n] -> [n][k]
        if (t >= NL * 4096) return;
        int layer = t / 4096, rem = t % 4096, n = rem >> 6, k = rem & 63;
        float v = Wo[(size_t)layer * 4096 + k * 64 + n];
        split2(v, g_woT_h[t], g_woT_l[t]);
    } else if (which == 2) {                // w1: [64k][2048n] -> [n][k]
        if (t >= NL * DFF * 64) return;
        int layer = t / (DFF * 64), rem = t % (DFF * 64), n = rem >> 6, k = rem & 63;
        float v = W1[(size_t)layer * DFF * 64 + k * DFF + n];
        split2(v, g_w1T_h[t], g_w1T_l[t]);
    } else {                                // w2: [2048k][64n] -> [c][n][kl]
        if (t >= NL * DFF * 64) return;
        int layer = t / (DFF * 64), rem = t % (DFF * 64);
        int c = rem / 4096, w = rem % 4096, n = w >> 6, kl = w & 63;
        float v = W2[(size_t)layer * DFF * 64 + (c * 64 + kl) * 64 + n];
        split2(v, g_w2T_h[t], g_w2T_l[t]);
    }
}

// ---------------- embed ----------------
__global__ void embed_kernel(const float* __restrict__ features,
                             const int* __restrict__ overlap_tag,
                             const int* __restrict__ poi_id,
                             const float* __restrict__ W_raw,
                             const float* __restrict__ b_raw,
                             const float* __restrict__ pos_tab,
                             const float* __restrict__ type_tab,
                             const float* __restrict__ poi_tab,
                             const float* __restrict__ overlap_tab,
                             const float* __restrict__ W_comb,
                             const float* __restrict__ b_comb,
                             float* __restrict__ x,
                             unsigned char* __restrict__ zero_mask)
{
    int bl = blockIdx.x;
    int l  = bl & (LL - 1);
    int s  = l >> 6;
    int v  = l & 63;
    int tid = threadIdx.x;  // 64

    __shared__ float concat[80];
    const float* f = features + (size_t)bl * 3;
    float f0 = f[0], f1 = f[1], f2 = f[2];

    concat[tid] = f0 * W_raw[tid] + f1 * W_raw[64 + tid] + f2 * W_raw[128 + tid] + b_raw[tid];
    if (tid < 8) {
        int ov = overlap_tag[bl];
        concat[64 + tid] = (ov == 0) ? 0.0f : overlap_tab[ov * 8 + tid];
        int poi = poi_id[bl];
        concat[72 + tid] = (poi == 0) ? 0.0f : poi_tab[poi * 8 + tid];
    }
    if (tid == 0) zero_mask[bl] = (f0 + f1 + f2 == 0.0f) ? 1 : 0;
    __syncthreads();

    float acc = b_comb[tid];
#pragma unroll
    for (int j = 0; j < 80; j++) acc += concat[j] * W_comb[j * EE + tid];
    acc += pos_tab[s * EE + tid] + type_tab[v * EE + tid];
    x[(size_t)bl * EE + tid] = acc;
}

// ---------------- QKV GEMM: x[128,64] @ WqkvT-chunk -> permuted [B][H][L][8] ----------------
__global__ __launch_bounds__(256) void gemm_qkv(const float* __restrict__ A,
                                                const __nv_bfloat16* __restrict__ WTh,
                                                const __nv_bfloat16* __restrict__ WTl,
                                                const float* __restrict__ bias,
                                                float* __restrict__ Qo,
                                                float* __restrict__ Ko,
                                                float* __restrict__ Vo)
{
    extern __shared__ __align__(16) char sm[];
    __nv_bfloat16* Ah = (__nv_bfloat16*)sm;             // 128*SP
    __nv_bfloat16* Al = (__nv_bfloat16*)(sm + 18432);
    __nv_bfloat16* Wh = (__nv_bfloat16*)(sm + 36864);   // 64*SP
    __nv_bfloat16* Wl = (__nv_bfloat16*)(sm + 46080);

    int tid = threadIdx.x;
    int w = tid >> 5, lane = tid & 31;
    int wm = w >> 1, wn = w & 1;
    int rm = wm * 32, cn = wn * 32;
    int row0 = blockIdx.y * 128;
    int sel = blockIdx.x;
    int gr = lane >> 2, gc = (lane & 3) * 2;

    for (int i = tid; i < 2048; i += 256) {
        int r = i >> 4, f4 = i & 15;
        float4 v = *(const float4*)&A[(size_t)(row0 + r) * 64 + f4 * 4];
        unsigned hp, lp;
        split_pair(v.x, v.y, hp, lp);
        *(unsigned*)&Ah[r * SP + f4 * 4] = hp;
        *(unsigned*)&Al[r * SP + f4 * 4] = lp;
        split_pair(v.z, v.w, hp, lp);
        *(unsigned*)&Ah[r * SP + f4 * 4 + 2] = hp;
        *(unsigned*)&Al[r * SP + f4 * 4 + 2] = lp;
    }
    const __nv_bfloat16* sh = WTh + sel * 4096;
    const __nv_bfloat16* sl = WTl + sel * 4096;
    for (int i = tid; i < 512; i += 256) {
        int n = i >> 3, p = i & 7;
        *(uint4*)&Wh[n * SP + p * 8] = *(const uint4*)&sh[n * 64 + p * 8];
        *(uint4*)&Wl[n * SP + p * 8] = *(const uint4*)&sl[n * 64 + p * 8];
    }
    __syncthreads();

    float acc[2][4][4];
#pragma unroll
    for (int i = 0; i < 2; i++)
#pragma unroll
        for (int j = 0; j < 4; j++)
#pragma unroll
            for (int r = 0; r < 4; r++) acc[i][j][r] = 0.0f;

#pragma unroll
    for (int kt = 0; kt < 4; kt++) {
        int kk = kt * 16;
        unsigned ah[2][4], al[2][4], bh[4][2], bl[4][2];
#pragma unroll
        for (int mi = 0; mi < 2; mi++) {
            int r = rm + mi * 16;
            ah[mi][0] = *(unsigned*)&Ah[(r + gr) * SP + kk + gc];
            ah[mi][1] = *(unsigned*)&Ah[(r + gr + 8) * SP + kk + gc];
            ah[mi][2] = *(unsigned*)&Ah[(r + gr) * SP + kk + gc + 8];
            ah[mi][3] = *(unsigned*)&Ah[(r + gr + 8) * SP + kk + gc + 8];
            al[mi][0] = *(unsigned*)&Al[(r + gr) * SP + kk + gc];
            al[mi][1] = *(unsigned*)&Al[(r + gr + 8) * SP + kk + gc];
            al[mi][2] = *(unsigned*)&Al[(r + gr) * SP + kk + gc + 8];
            al[mi][3] = *(unsigned*)&Al[(r + gr + 8) * SP + kk + gc + 8];
        }
#pragma unroll
        for (int ni = 0; ni < 4; ni++) {
            int n = cn + ni * 8 + gr;
            bh[ni][0] = *(unsigned*)&Wh[n * SP + kk + gc];
            bh[ni][1] = *(unsigned*)&Wh[n * SP + kk + gc + 8];
            bl[ni][0] = *(unsigned*)&Wl[n * SP + kk + gc];
            bl[ni][1] = *(unsigned*)&Wl[n * SP + kk + gc + 8];
        }
#pragma unroll
        for (int mi = 0; mi < 2; mi++)
#pragma unroll
            for (int ni = 0; ni < 4; ni++) {
                mma_bf16(acc[mi][ni], ah[mi], bh[ni]);
                mma_bf16(acc[mi][ni], al[mi], bh[ni]);
                mma_bf16(acc[mi][ni], ah[mi], bl[ni]);
            }
    }

    int b = row0 >> 10;
    float* outp = (sel == 0) ? Qo : ((sel == 1) ? Ko : Vo);
#pragma unroll
    for (int mi = 0; mi < 2; mi++) {
        int r0 = rm + mi * 16 + gr;
        int l0 = (row0 + r0) & (LL - 1);
#pragma unroll
        for (int ni = 0; ni < 4; ni++) {
            int loc = cn + ni * 8 + gc;
            int h = loc >> 3, d = loc & 7;
            float b0 = bias[sel * 64 + loc], b1v = bias[sel * 64 + loc + 1];
            size_t base = ((size_t)(b * 8 + h) * LL);
            *(float2*)&outp[(base + l0) * 8 + d] =
                make_float2(acc[mi][ni][0] + b0, acc[mi][ni][1] + b1v);
            *(float2*)&outp[(base + l0 + 8) * 8 + d] =
                make_float2(acc[mi][ni][2] + b0, acc[mi][ni][3] + b1v);
        }
    }
}

// ---------------- Wo projection + residual + LN1 ----------------
__global__ __launch_bounds__(256) void gemm_wo_ln(const float* __restrict__ A,
                                                  const __nv_bfloat16* __restrict__ WTh,
                                                  const __nv_bfloat16* __restrict__ WTl,
                                                  const float* __restrict__ bias,
                                                  float* __restrict__ x,
                                                  const float* __restrict__ ln_s,
                                                  const float* __restrict__ ln_b)
{
    extern __shared__ __align__(16) char sm[];
    __nv_bfloat16* Ah = (__nv_bfloat16*)sm;             // 64*SP
    __nv_bfloat16* Al = (__nv_bfloat16*)(sm + 9216);
    __nv_bfloat16* Wh = (__nv_bfloat16*)(sm + 18432);
    __nv_bfloat16* Wl = (__nv_bfloat16*)(sm + 27648);
    float* buf = (float*)(sm + 36864);                  // 64*65 floats

    int tid = threadIdx.x;
    int w = tid >> 5, lane = tid & 31;
    int wm = w >> 1, wn = w & 1;
    int rm = wm * 16, cn = wn * 32;
    int row0 = blockIdx.x * 64;
    int gr = lane >> 2, gc = (lane & 3) * 2;

    for (int i = tid; i < 1024; i += 256) {
        int r = i >> 4, f4 = i & 15;
        float4 v = *(const float4*)&A[(size_t)(row0 + r) * 64 + f4 * 4];
        unsigned hp, lp;
        split_pair(v.x, v.y, hp, lp);
        *(unsigned*)&Ah[r * SP + f4 * 4] = hp;
        *(unsigned*)&Al[r * SP + f4 * 4] = lp;
        split_pair(v.z, v.w, hp, lp);
        *(unsigned*)&Ah[r * SP + f4 * 4 + 2] = hp;
        *(unsigned*)&Al[r * SP + f4 * 4 + 2] = lp;
    }
    for (int i = tid; i < 512; i += 256) {
        int n = i >> 3, p = i & 7;
        *(uint4*)&Wh[n * SP + p * 8] = *(const uint4*)&WTh[n * 64 + p * 8];
        *(uint4*)&Wl[n * SP + p * 8] = *(const uint4*)&WTl[n * 64 + p * 8];
    }
    __syncthreads();

    float acc[4][4];
#pragma unroll
    for (int j = 0; j < 4; j++)
#pragma unroll
        for (int r = 0; r < 4; r++) acc[j][r] = 0.0f;

#pragma unroll
    for (int kt = 0; kt < 4; kt++) {
        int kk = kt * 16;
        unsigned ah[4], al[4], bh[4][2], bl[4][2];
        ah[0] = *(unsigned*)&Ah[(rm + gr) * SP + kk + gc];
        ah[1] = *(unsigned*)&Ah[(rm + gr + 8) * SP + kk + gc];
        ah[2] = *(unsigned*)&Ah[(rm + gr) * SP + kk + gc + 8];
        ah[3] = *(unsigned*)&Ah[(rm + gr + 8) * SP + kk + gc + 8];
        al[0] = *(unsigned*)&Al[(rm + gr) * SP + kk + gc];
        al[1] = *(unsigned*)&Al[(rm + gr + 8) * SP + kk + gc];
        al[2] = *(unsigned*)&Al[(rm + gr) * SP + kk + gc + 8];
        al[3] = *(unsigned*)&Al[(rm + gr + 8) * SP + kk + gc + 8];
#pragma unroll
        for (int ni = 0; ni < 4; ni++) {
            int n = cn + ni * 8 + gr;
            bh[ni][0] = *(unsigned*)&Wh[n * SP + kk + gc];
            bh[ni][1] = *(unsigned*)&Wh[n * SP + kk + gc + 8];
            bl[ni][0] = *(unsigned*)&Wl[n * SP + kk + gc];
            bl[ni][1] = *(unsigned*)&Wl[n * SP + kk + gc + 8];
        }
#pragma unroll
        for (int ni = 0; ni < 4; ni++) {
            mma_bf16(acc[ni], ah, bh[ni]);
            mma_bf16(acc[ni], al, bh[ni]);
            mma_bf16(acc[ni], ah, bl[ni]);
        }
    }

#pragma unroll
    for (int ni = 0; ni < 4; ni++) {
        int c = cn + ni * 8 + gc;
        float b0 = bias[c], b1v = bias[c + 1];
        buf[(rm + gr) * 65 + c] = acc[ni][0] + b0;
        buf[(rm + gr) * 65 + c + 1] = acc[ni][1] + b1v;
        buf[(rm + gr + 8) * 65 + c] = acc[ni][2] + b0;
        buf[(rm + gr + 8) * 65 + c + 1] = acc[ni][3] + b1v;
    }
    __syncthreads();

    for (int rr = 0; rr < 8; rr++) {
        int row = w * 8 + rr;
        size_t go = (size_t)(row0 + row) * 64;
        float y0 = buf[row * 65 + lane] + x[go + lane];
        float y1 = buf[row * 65 + lane + 32] + x[go + lane + 32];
        float mean = warp_sum32(y0 + y1) * (1.0f / 64.0f);
        float d0 = y0 - mean, d1 = y1 - mean;
        float var = warp_sum32(d0 * d0 + d1 * d1) * (1.0f / 64.0f);
        float inv = rsqrtf(var + 1e-5f);
        x[go + lane] = d0 * inv * ln_s[lane] + ln_b[lane];
        x[go + lane + 32] = d1 * inv * ln_s[lane + 32] + ln_b[lane + 32];
    }
}

// ---------------- fused FFN, 128 rows/block, cp.async double-buffered weights ----------------
#define XH_OFF 0
#define XL_OFF 18432
#define HH_OFF 36864
#define HL_OFF 55296
#define WS_OFF 73728
#define WS_STRIDE 36864
#define BUF_OFF 73728
#define FFN_SMEM 147456

__global__ __launch_bounds__(512) void ffn_fused(const float* __restrict__ xin,
                                                 const __nv_bfloat16* __restrict__ w1h,
                                                 const __nv_bfloat16* __restrict__ w1l,
                                                 const __nv_bfloat16* __restrict__ w2h,
                                                 const __nv_bfloat16* __restrict__ w2l,
                                                 const float* __restrict__ b1,
                                                 const float* __restrict__ b2,
                                                 float* __restrict__ x,
                                                 const float* __restrict__ ln_s,
                                                 const float* __restrict__ ln_b)
{
    extern __shared__ __align__(16) char sm[];
    __nv_bfloat16* Xh = (__nv_bfloat16*)(sm + XH_OFF);
    __nv_bfloat16* Xl = (__nv_bfloat16*)(sm + XL_OFF);
    __nv_bfloat16* Hh = (__nv_bfloat16*)(sm + HH_OFF);
    __nv_bfloat16* Hl = (__nv_bfloat16*)(sm + HL_OFF);
    float* buf = (float*)(sm + BUF_OFF);
    unsigned smem_base = (unsigned)__cvta_generic_to_shared(sm);

    int tid = threadIdx.x;
    int w = tid >> 5, lane = tid & 31;
    int wm = w >> 1, wn = w & 1;
    int rm = wm * 16, cn = wn * 32;
    int row0 = blockIdx.x * 128;
    int gr = lane >> 2, gc = (lane & 3) * 2;

    // load + split X tile 128x64
    for (int i = tid; i < 2048; i += 512) {
        int r = i >> 4, f4 = i & 15;
        float4 v = *(const float4*)&xin[(size_t)(row0 + r) * 64 + f4 * 4];
        unsigned hp, lp;
        split_pair(v.x, v.y, hp, lp);
        *(unsigned*)&Xh[r * SP + f4 * 4] = hp;
        *(unsigned*)&Xl[r * SP + f4 * 4] = lp;
        split_pair(v.z, v.w, hp, lp);
        *(unsigned*)&Xh[r * SP + f4 * 4 + 2] = hp;
        *(unsigned*)&Xl[r * SP + f4 * 4 + 2] = lp;
    }

    // async weight chunk loader: one 16B copy per thread per buffer
    int wn8 = tid >> 3, wp = tid & 7;  // 64 rows x 8 segs = 512
    unsigned dofs = (unsigned)(wn8 * SP * 2 + wp * 16);
    int sofs = wn8 * 64 + wp * 8;

    float acc2[4][4];
#pragma unroll
    for (int j = 0; j < 4; j++)
#pragma unroll
        for (int r = 0; r < 4; r++) acc2[j][r] = 0.0f;

    // preload chunk 0 into stage 0
    {
        unsigned st = smem_base + WS_OFF;
        CP_ASYNC16(st + dofs,         w1h + sofs);
        CP_ASYNC16(st + 9216 + dofs,  w1l + sofs);
        CP_ASYNC16(st + 18432 + dofs, w2h + sofs);
        CP_ASYNC16(st + 27648 + dofs, w2l + sofs);
    }
    CP_COMMIT();

    for (int c = 0; c < 32; c++) {
        int s = c & 1;
        if (c + 1 < 32) {
            unsigned st = smem_base + WS_OFF + (s ^ 1) * WS_STRIDE;
            int src = (c + 1) * 4096 + sofs;
            CP_ASYNC16(st + dofs,         w1h + src);
            CP_ASYNC16(st + 9216 + dofs,  w1l + src);
            CP_ASYNC16(st + 18432 + dofs, w2h + src);
            CP_ASYNC16(st + 27648 + dofs, w2l + src);
        }
        CP_COMMIT();
        CP_WAIT1();
        __syncthreads();

        __nv_bfloat16* W1h = (__nv_bfloat16*)(sm + WS_OFF + s * WS_STRIDE);
        __nv_bfloat16* W1l = (__nv_bfloat16*)(sm + WS_OFF + s * WS_STRIDE + 9216);
        __nv_bfloat16* W2h = (__nv_bfloat16*)(sm + WS_OFF + s * WS_STRIDE + 18432);
        __nv_bfloat16* W2l = (__nv_bfloat16*)(sm + WS_OFF + s * WS_STRIDE + 27648);

        // GEMM1: h = relu(x @ W1c + b1c)
        float hacc[4][4];
#pragma unroll
        for (int j = 0; j < 4; j++)
#pragma unroll
            for (int r = 0; r < 4; r++) hacc[j][r] = 0.0f;

#pragma unroll
        for (int kt = 0; kt < 4; kt++) {
            int kk = kt * 16;
            unsigned ah[4], al[4], bh[4][2], bl[4][2];
            ah[0] = *(unsigned*)&Xh[(rm + gr) * SP + kk + gc];
            ah[1] = *(unsigned*)&Xh[(rm + gr + 8) * SP + kk + gc];
            ah[2] = *(unsigned*)&Xh[(rm + gr) * SP + kk + gc + 8];
            ah[3] = *(unsigned*)&Xh[(rm + gr + 8) * SP + kk + gc + 8];
            al[0] = *(unsigned*)&Xl[(rm + gr) * SP + kk + gc];
            al[1] = *(unsigned*)&Xl[(rm + gr + 8) * SP + kk + gc];
            al[2] = *(unsigned*)&Xl[(rm + gr) * SP + kk + gc + 8];
            al[3] = *(unsigned*)&Xl[(rm + gr + 8) * SP + kk + gc + 8];
#pragma unroll
            for (int ni = 0; ni < 4; ni++) {
                int n = cn + ni * 8 + gr;
                bh[ni][0] = *(unsigned*)&W1h[n * SP + kk + gc];
                bh[ni][1] = *(unsigned*)&W1h[n * SP + kk + gc + 8];
                bl[ni][0] = *(unsigned*)&W1l[n * SP + kk + gc];
                bl[ni][1] = *(unsigned*)&W1l[n * SP + kk + gc + 8];
            }
#pragma unroll
            for (int ni = 0; ni < 4; ni++) {
                mma_bf16(hacc[ni], ah, bh[ni]);
                mma_bf16(hacc[ni], al, bh[ni]);
                mma_bf16(hacc[ni], ah, bl[ni]);
            }
        }

#pragma unroll
        for (int ni = 0; ni < 4; ni++) {
            int cl = cn + ni * 8 + gc;
            int cg = c * 64 + cl;
            float v0 = fmaxf(hacc[ni][0] + b1[cg], 0.0f);
            float v1 = fmaxf(hacc[ni][1] + b1[cg + 1], 0.0f);
            float v2 = fmaxf(hacc[ni][2] + b1[cg], 0.0f);
            float v3 = fmaxf(hacc[ni][3] + b1[cg + 1], 0.0f);
            unsigned hp, lp;
            split_pair(v0, v1, hp, lp);
            *(unsigned*)&Hh[(rm + gr) * SP + cl] = hp;
            *(unsigned*)&Hl[(rm + gr) * SP + cl] = lp;
            split_pair(v2, v3, hp, lp);
            *(unsigned*)&Hh[(rm + gr + 8) * SP + cl] = hp;
            *(unsigned*)&Hl[(rm + gr + 8) * SP + cl] = lp;
        }
        __syncthreads();

        // GEMM2: acc2 += h @ W2c
#pragma unroll
        for (int kt = 0; kt < 4; kt++) {
            int kk = kt * 16;
            unsigned ah[4], al[4], bh[4][2], bl[4][2];
            ah[0] = *(unsigned*)&Hh[(rm + gr) * SP + kk + gc];
            ah[1] = *(unsigned*)&Hh[(rm + gr + 8) * SP + kk + gc];
            ah[2] = *(unsigned*)&Hh[(rm + gr) * SP + kk + gc + 8];
            ah[3] = *(unsigned*)&Hh[(rm + gr + 8) * SP + kk + gc + 8];
            al[0] = *(unsigned*)&Hl[(rm + gr) * SP + kk + gc];
            al[1] = *(unsigned*)&Hl[(rm + gr + 8) * SP + kk + gc];
            al[2] = *(unsigned*)&Hl[(rm + gr) * SP + kk + gc + 8];
            al[3] = *(unsigned*)&Hl[(rm + gr + 8) * SP + kk + gc + 8];
#pragma unroll
            for (int ni = 0; ni < 4; ni++) {
                int n = cn + ni * 8 + gr;
                bh[ni][0] = *(unsigned*)&W2h[n * SP + kk + gc];
                bh[ni][1] = *(unsigned*)&W2h[n * SP + kk + gc + 8];
                bl[ni][0] = *(unsigned*)&W2l[n * SP + kk + gc];
                bl[ni][1] = *(unsigned*)&W2l[n * SP + kk + gc + 8];
            }
#pragma unroll
            for (int ni = 0; ni < 4; ni++) {
                mma_bf16(acc2[ni], ah, bh[ni]);
                mma_bf16(acc2[ni], al, bh[ni]);
                mma_bf16(acc2[ni], ah, bl[ni]);
            }
        }
        __syncthreads();
    }

    // epilogue: + b2 -> buf, + residual, LN2
#pragma unroll
    for (int ni = 0; ni < 4; ni++) {
        int cc = cn + ni * 8 + gc;
        float b0 = b2[cc], b1v = b2[cc + 1];
        buf[(rm + gr) * 65 + cc] = acc2[ni][0] + b0;
        buf[(rm + gr) * 65 + cc + 1] = acc2[ni][1] + b1v;
        buf[(rm + gr + 8) * 65 + cc] = acc2[ni][2] + b0;
        buf[(rm + gr + 8) * 65 + cc + 1] = acc2[ni][3] + b1v;
    }
    __syncthreads();

    for (int rr = 0; rr < 8; rr++) {
        int row = w * 8 + rr;
        size_t go = (size_t)(row0 + row) * 64;
        float y0 = buf[row * 65 + lane] + xin[go + lane];
        float y1 = buf[row * 65 + lane + 32] + xin[go + lane + 32];
        float mean = warp_sum32(y0 + y1) * (1.0f / 64.0f);
        float d0 = y0 - mean, d1 = y1 - mean;
        float var = warp_sum32(d0 * d0 + d1 * d1) * (1.0f / 64.0f);
        float inv = rsqrtf(var + 1e-5f);
        x[go + lane] = d0 * inv * ln_s[lane] + ln_b[lane];
        x[go + lane + 32] = d1 * inv * ln_s[lane + 32] + ln_b[lane + 32];
    }
}

// ---------------- attention (structured sparse, permuted QKV) ----------------
__device__ __forceinline__ void attn_step(int k, const float* __restrict__ Ks,
                                          const float* __restrict__ Vs,
                                          const unsigned char* __restrict__ zs,
                                          const float4& q0, const float4& q1,
                                          float scale, float& m, float& ssum,
                                          float4& a0, float4& a1)
{
    if (zs[k]) return;
    const float4* K4 = (const float4*)(Ks + k * 8);
    float4 k0 = K4[0], k1 = K4[1];
    float dot = (q0.x * k0.x + q0.y * k0.y + q0.z * k0.z + q0.w * k0.w +
                 q1.x * k1.x + q1.y * k1.y + q1.z * k1.z + q1.w * k1.w) * scale;
    const float4* V4 = (const float4*)(Vs + k * 8);
    float4 v0 = V4[0], v1 = V4[1];
    if (dot > m) {
        float cc = __expf(m - dot);
        ssum = ssum * cc + 1.0f;
        a0.x = a0.x * cc + v0.x; a0.y = a0.y * cc + v0.y;
        a0.z = a0.z * cc + v0.z; a0.w = a0.w * cc + v0.w;
        a1.x = a1.x * cc + v1.x; a1.y = a1.y * cc + v1.y;
        a1.z = a1.z * cc + v1.z; a1.w = a1.w * cc + v1.w;
        m = dot;
    } else {
        float wgt = __expf(dot - m);
        ssum += wgt;
        a0.x += wgt * v0.x; a0.y += wgt * v0.y; a0.z += wgt * v0.z; a0.w += wgt * v0.w;
        a1.x += wgt * v1.x; a1.y += wgt * v1.y; a1.z += wgt * v1.z; a1.w += wgt * v1.w;
    }
}

__global__ void attn_kernel(const float* __restrict__ Qg,
                            const float* __restrict__ Kg,
                            const float* __restrict__ Vg,
                            const unsigned char* __restrict__ zero_mask,
                            float* __restrict__ out)
{
    extern __shared__ float smf[];
    float* Ks = smf;
    float* Vs = smf + 8192;
    unsigned char* zs = (unsigned char*)(smf + 16384);

    int b = blockIdx.x >> 3;
    int h = blockIdx.x & 7;
    int tid = threadIdx.x;  // 512
    size_t base = (size_t)(b * 8 + h) * LL * 8;

    for (int i = tid; i < 2048; i += 512) {
        ((float4*)Ks)[i] = ((const float4*)(Kg + base))[i];
        ((float4*)Vs)[i] = ((const float4*)(Vg + base))[i];
    }
    for (int i = tid; i < 1024; i += 512) zs[i] = zero_mask[b * LL + i];
    __syncthreads();

    const float scale = 0.35355339059327373f;

    for (int q = tid; q < LL; q += 512) {
        int tq = q >> 6, vq = q & 63;
        float4 q0 = ((const float4*)(Qg + base + q * 8))[0];
        float4 q1 = ((const float4*)(Qg + base + q * 8))[1];

        float m = -1e30f, ssum = 0.0f;
        float4 a0 = make_float4(0, 0, 0, 0), a1 = make_float4(0, 0, 0, 0);

        int kb = tq << 6;
        for (int j = 0; j < 64; j++)
            attn_step(kb + j, Ks, Vs, zs, q0, q1, scale, m, ssum, a0, a1);
        for (int t = 0; t < 16; t++) {
            if (t == tq) continue;
            attn_step((t << 6) + vq, Ks, Vs, zs, q0, q1, scale, m, ssum, a0, a1);
        }

        float inv = 1.0f / ssum;
        float* o = out + ((size_t)(b * LL + q)) * EE + h * 8;
        *(float4*)o = make_float4(a0.x * inv, a0.y * inv, a0.z * inv, a0.w * inv);
        *(float4*)(o + 4) = make_float4(a1.x * inv, a1.y * inv, a1.z * inv, a1.w * inv);
    }
}

// ---------------- head ----------------
__global__ void head_kernel(const float* __restrict__ x,
                            const float* __restrict__ W_head,
                            const float* __restrict__ b_head,
                            float* __restrict__ out)
{
    int b = blockIdx.x;
    int tid = threadIdx.x;  // 192
    int v = tid / 3, c = tid % 3;
    const float* row = x + ((size_t)(b * LL + (SS - 1) * VV + v)) * EE;
    float acc = b_head[c];
#pragma unroll
    for (int e = 0; e < EE; e++) acc += row[e] * W_head[e * 3 + c];
    out[b * (VV * 3) + tid] = acc;
}

// ---------------- launch ----------------
extern "C" void kernel_launch(void* const* d_in, const int* in_sizes, int n_in,
                              void* d_out, int out_size)
{
    const float* features    = (const float*)d_in[0];
    const int*   overlap_tag = (const int*)d_in[1];
    const int*   poi_id      = (const int*)d_in[2];
    const float* W_raw       = (const float*)d_in[3];
    const float* b_raw       = (const float*)d_in[4];
    const float* pos_tab     = (const float*)d_in[5];
    const float* type_tab    = (const float*)d_in[6];
    const float* poi_tab     = (const float*)d_in[7];
    const float* overlap_tab = (const float*)d_in[8];
    const float* W_comb      = (const float*)d_in[9];
    const float* b_comb      = (const float*)d_in[10];
    const float* Wqkv        = (const float*)d_in[11];
    const float* bqkv        = (const float*)d_in[12];
    const float* Wo          = (const float*)d_in[13];
    const float* bo          = (const float*)d_in[14];
    const float* ln1_s       = (const float*)d_in[15];
    const float* ln1_b       = (const float*)d_in[16];
    const float* W1          = (const float*)d_in[17];
    const float* b1          = (const float*)d_in[18];
    const float* W2          = (const float*)d_in[19];
    const float* b2          = (const float*)d_in[20];
    const float* ln2_s       = (const float*)d_in[21];
    const float* ln2_b       = (const float*)d_in[22];
    const float* W_head      = (const float*)d_in[23];
    const float* b_head      = (const float*)d_in[24];
    float* out = (float*)d_out;

    float *x, *qb, *kb, *vb, *attn;
    unsigned char* zero;
    __nv_bfloat16 *qkvh, *qkvl, *woh, *wol, *w1h, *w1l, *w2h, *w2l;
    cudaGetSymbolAddress((void**)&x,    g_x);
    cudaGetSymbolAddress((void**)&qb,   g_q);
    cudaGetSymbolAddress((void**)&kb,   g_k);
    cudaGetSymbolAddress((void**)&vb,   g_v);
    cudaGetSymbolAddress((void**)&attn, g_attn);
    cudaGetSymbolAddress((void**)&zero, g_zero);
    cudaGetSymbolAddress((void**)&qkvh, g_qkvT_h);
    cudaGetSymbolAddress((void**)&qkvl, g_qkvT_l);
    cudaGetSymbolAddress((void**)&woh,  g_woT_h);
    cudaGetSymbolAddress((void**)&wol,  g_woT_l);
    cudaGetSymbolAddress((void**)&w1h,  g_w1T_h);
    cudaGetSymbolAddress((void**)&w1l,  g_w1T_l);
    cudaGetSymbolAddress((void**)&w2h,  g_w2T_h);
    cudaGetSymbolAddress((void**)&w2l,  g_w2T_l);

    const int ATTN_SMEM = 16384 * 4 + 1024;
    const int QKV_SMEM  = 55296;
    const int WO_SMEM   = 36864 + 64 * 65 * 4;
    cudaFuncSetAttribute(attn_kernel, cudaFuncAttributeMaxDynamicSharedMemorySize, ATTN_SMEM);
    cudaFuncSetAttribute(ffn_fused, cudaFuncAttributeMaxDynamicSharedMemorySize, FFN_SMEM);
    cudaFuncSetAttribute(gemm_qkv, cudaFuncAttributeMaxDynamicSharedMemorySize, QKV_SMEM);
    cudaFuncSetAttribute(gemm_wo_ln, cudaFuncAttributeMaxDynamicSharedMemorySize, WO_SMEM);

    prep_weights<<<dim3(2048, 4), 256>>>(Wqkv, Wo, W1, W2);

    embed_kernel<<<ML, 64>>>(features, overlap_tag, poi_id, W_raw, b_raw,
                             pos_tab, type_tab, poi_tab, overlap_tab,
                             W_comb, b_comb, x, zero);

    for (int l = 0; l < NL; l++) {
        gemm_qkv<<<dim3(3, ML / 128), 256, QKV_SMEM>>>(
            x, qkvh + l * 12288, qkvl + l * 12288, bqkv + l * 192, qb, kb, vb);
        attn_kernel<<<BB * HH, 512, ATTN_SMEM>>>(qb, kb, vb, zero, attn);
        gemm_wo_ln<<<ML / 64, 256, WO_SMEM>>>(
            attn, woh + l * 4096, wol + l * 4096, bo + l * EE,
            x, ln1_s + l * EE, ln1_b + l * EE);
        ffn_fused<<<ML / 128, 512, FFN_SMEM>>>(
            x, w1h + l * DFF * 64, w1l + l * DFF * 64,
            w2h + l * DFF * 64, w2l + l * DFF * 64,
            b1 + l * DFF, b2 + l * EE,
            x, ln2_s + l * EE, ln2_b + l * EE);
    }

    head_kernel<<<BB, VV * 3>>>(x, W_head, b_head, out);
}

// round 5
// speedup vs baseline: 5.0877x; 1.1210x over previous
#include <cuda_runtime.h>
#include <cuda_fp16.h>
#include <math.h>

#define BB 16
#define SS 16
#define VV 64
#define EE 64
#define HH 8
#define NL 4
#define DFF 2048
#define LL 1024
#define ML (BB*LL)
#define SPH 72   // smem row stride in halves (64 data + 8 pad) = 144 bytes

// ---------------- scratch ----------------
__device__ float g_x[ML * EE];            // fp32 residual stream
__device__ __half g_xh[ML * EE];          // fp16 copy of x
__device__ float g_q[ML * EE];
__device__ float g_k[ML * EE];
__device__ float g_v[ML * EE];
__device__ __half g_attnh[ML * EE];       // attention output (fp16)
__device__ unsigned char g_zero[ML];

// pre-converted transposed fp16 weights ([n][k])
__device__ __align__(256) __half g_qkvT[NL * 192 * 64];
__device__ __align__(256) __half g_woT[NL * 64 * 64];
__device__ __align__(256) __half g_w1T[NL * DFF * 64];
__device__ __align__(256) __half g_w2T[NL * DFF * 64];

// ---------------- helpers ----------------
__device__ __forceinline__ unsigned pack2h(float a, float b) {
    __half2 h = __floats2half2_rn(a, b);
    return *(unsigned*)&h;
}
__device__ __forceinline__ void mma_f16(float* c, const unsigned* a, const unsigned* b) {
    asm volatile(
        "mma.sync.aligned.m16n8k16.row.col.f32.f16.f16.f32 "
        "{%0,%1,%2,%3}, {%4,%5,%6,%7}, {%8,%9}, {%0,%1,%2,%3};\n"
        : "+f"(c[0]), "+f"(c[1]), "+f"(c[2]), "+f"(c[3])
        : "r"(a[0]), "r"(a[1]), "r"(a[2]), "r"(a[3]), "r"(b[0]), "r"(b[1]));
}
__device__ __forceinline__ float warp_sum32(float v) {
#pragma unroll
    for (int o = 16; o > 0; o >>= 1) v += __shfl_xor_sync(0xffffffffu, v, o);
    return v;
}
#define CP_ASYNC16(dst, src) \
    asm volatile("cp.async.ca.shared.global [%0], [%1], 16;\n" :: "r"(dst), "l"(src))
#define CP_COMMIT() asm volatile("cp.async.commit_group;\n")
#define CP_WAIT1()  asm volatile("cp.async.wait_group 1;\n")

// ---------------- weight prep ----------------
__global__ void prep_weights(const float* __restrict__ Wqkv,
                             const float* __restrict__ Wo,
                             const float* __restrict__ W1,
                             const float* __restrict__ W2)
{
    int t = blockIdx.x * 256 + threadIdx.x;
    int which = blockIdx.y;
    if (which == 0) {                       // qkv: [64k][192n] -> [n][k]
        if (t >= NL * 12288) return;
        int layer = t / 12288, rem = t % 12288, n = rem >> 6, k = rem & 63;
        g_qkvT[t] = __float2half_rn(Wqkv[(size_t)layer * 12288 + k * 192 + n]);
    } else if (which == 1) {                // wo: [64k][64n] -> [n][k]
        if (t >= NL * 4096) return;
        int layer = t / 4096, rem = t % 4096, n = rem >> 6, k = rem & 63;
        g_woT[t] = __float2half_rn(Wo[(size_t)layer * 4096 + k * 64 + n]);
    } else if (which == 2) {                // w1: [64k][2048n] -> [c][n][k]
        if (t >= NL * DFF * 64) return;
        int layer = t / (DFF * 64), rem = t % (DFF * 64), n = rem >> 6, k = rem & 63;
        g_w1T[t] = __float2half_rn(W1[(size_t)layer * DFF * 64 + k * DFF + n]);
    } else {                                // w2: [2048k][64n] -> [c][n][kl]
        if (t >= NL * DFF * 64) return;
        int layer = t / (DFF * 64), rem = t % (DFF * 64);
        int c = rem / 4096, w = rem % 4096, n = w >> 6, kl = w & 63;
        g_w2T[t] = __float2half_rn(W2[(size_t)layer * DFF * 64 + (c * 64 + kl) * 64 + n]);
    }
}

// ---------------- embed ----------------
__global__ void embed_kernel(const float* __restrict__ features,
                             const int* __restrict__ overlap_tag,
                             const int* __restrict__ poi_id,
                             const float* __restrict__ W_raw,
                             const float* __restrict__ b_raw,
                             const float* __restrict__ pos_tab,
                             const float* __restrict__ type_tab,
                             const float* __restrict__ poi_tab,
                             const float* __restrict__ overlap_tab,
                             const float* __restrict__ W_comb,
                             const float* __restrict__ b_comb,
                             float* __restrict__ x,
                             __half* __restrict__ xh,
                             unsigned char* __restrict__ zero_mask)
{
    int bl = blockIdx.x;
    int l  = bl & (LL - 1);
    int s  = l >> 6;
    int v  = l & 63;
    int tid = threadIdx.x;  // 64

    __shared__ float concat[80];
    const float* f = features + (size_t)bl * 3;
    float f0 = f[0], f1 = f[1], f2 = f[2];

    concat[tid] = f0 * W_raw[tid] + f1 * W_raw[64 + tid] + f2 * W_raw[128 + tid] + b_raw[tid];
    if (tid < 8) {
        int ov = overlap_tag[bl];
        concat[64 + tid] = (ov == 0) ? 0.0f : overlap_tab[ov * 8 + tid];
        int poi = poi_id[bl];
        concat[72 + tid] = (poi == 0) ? 0.0f : poi_tab[poi * 8 + tid];
    }
    if (tid == 0) zero_mask[bl] = (f0 + f1 + f2 == 0.0f) ? 1 : 0;
    __syncthreads();

    float acc = b_comb[tid];
#pragma unroll
    for (int j = 0; j < 80; j++) acc += concat[j] * W_comb[j * EE + tid];
    acc += pos_tab[s * EE + tid] + type_tab[v * EE + tid];
    x[(size_t)bl * EE + tid] = acc;
    xh[(size_t)bl * EE + tid] = __float2half_rn(acc);
}

// ---------------- QKV GEMM (fp16): xh[128,64] @ WT-chunk -> permuted fp32 [B][H][L][8] ----------------
__global__ __launch_bounds__(256) void gemm_qkv(const __half* __restrict__ Xh,
                                                const __half* __restrict__ WT,
                                                const float* __restrict__ bias,
                                                float* __restrict__ Qo,
                                                float* __restrict__ Ko,
                                                float* __restrict__ Vo)
{
    __shared__ __align__(16) __half As[128 * SPH];
    __shared__ __align__(16) __half Ws[64 * SPH];

    int tid = threadIdx.x;
    int w = tid >> 5, lane = tid & 31;
    int wm = w >> 1, wn = w & 1;
    int rm = wm * 32, cn = wn * 32;
    int row0 = blockIdx.y * 128;
    int sel = blockIdx.x;
    int gr = lane >> 2, gc = (lane & 3) * 2;

    for (int i = tid; i < 1024; i += 256) {
        int r = i >> 3, seg = i & 7;
        *(uint4*)&As[r * SPH + seg * 8] = *(const uint4*)&Xh[(size_t)(row0 + r) * 64 + seg * 8];
    }
    const __half* src = WT + sel * 4096;
    for (int i = tid; i < 512; i += 256) {
        int n = i >> 3, seg = i & 7;
        *(uint4*)&Ws[n * SPH + seg * 8] = *(const uint4*)&src[n * 64 + seg * 8];
    }
    __syncthreads();

    float acc[2][4][4];
#pragma unroll
    for (int i = 0; i < 2; i++)
#pragma unroll
        for (int j = 0; j < 4; j++)
#pragma unroll
            for (int r = 0; r < 4; r++) acc[i][j][r] = 0.0f;

#pragma unroll
    for (int kt = 0; kt < 4; kt++) {
        int kk = kt * 16;
        unsigned a[2][4], b[4][2];
#pragma unroll
        for (int mi = 0; mi < 2; mi++) {
            int r = rm + mi * 16;
            a[mi][0] = *(unsigned*)&As[(r + gr) * SPH + kk + gc];
            a[mi][1] = *(unsigned*)&As[(r + gr + 8) * SPH + kk + gc];
            a[mi][2] = *(unsigned*)&As[(r + gr) * SPH + kk + gc + 8];
            a[mi][3] = *(unsigned*)&As[(r + gr + 8) * SPH + kk + gc + 8];
        }
#pragma unroll
        for (int ni = 0; ni < 4; ni++) {
            int n = cn + ni * 8 + gr;
            b[ni][0] = *(unsigned*)&Ws[n * SPH + kk + gc];
            b[ni][1] = *(unsigned*)&Ws[n * SPH + kk + gc + 8];
        }
#pragma unroll
        for (int mi = 0; mi < 2; mi++)
#pragma unroll
            for (int ni = 0; ni < 4; ni++)
                mma_f16(acc[mi][ni], a[mi], b[ni]);
    }

    int b = row0 >> 10;
    float* outp = (sel == 0) ? Qo : ((sel == 1) ? Ko : Vo);
#pragma unroll
    for (int mi = 0; mi < 2; mi++) {
        int r0 = rm + mi * 16 + gr;
        int l0 = (row0 + r0) & (LL - 1);
#pragma unroll
        for (int ni = 0; ni < 4; ni++) {
            int loc = cn + ni * 8 + gc;
            int h = loc >> 3, d = loc & 7;
            float b0 = bias[sel * 64 + loc], b1v = bias[sel * 64 + loc + 1];
            size_t base = ((size_t)(b * 8 + h) * LL);
            *(float2*)&outp[(base + l0) * 8 + d] =
                make_float2(acc[mi][ni][0] + b0, acc[mi][ni][1] + b1v);
            *(float2*)&outp[(base + l0 + 8) * 8 + d] =
                make_float2(acc[mi][ni][2] + b0, acc[mi][ni][3] + b1v);
        }
    }
}

// ---------------- attention: structured sparse, max-free softmax ----------------
__global__ __launch_bounds__(256) void attn_kernel(const float* __restrict__ Qg,
                                                   const float* __restrict__ Kg,
                                                   const float* __restrict__ Vg,
                                                   const unsigned char* __restrict__ zero_mask,
                                                   __half* __restrict__ out)
{
    extern __shared__ float smf[];
    float* Ks = smf;
    float* Vs = smf + 8192;
    unsigned char* zs = (unsigned char*)(smf + 16384);

    int bid = blockIdx.x;          // 512 blocks: (b*8+h)*4 + part
    int part = bid & 3;
    int bh = bid >> 2;
    int b = bh >> 3, h = bh & 7;
    int tid = threadIdx.x;         // 256
    size_t base = (size_t)bh * LL * 8;

    for (int i = tid; i < 2048; i += 256) {
        ((float4*)Ks)[i] = ((const float4*)(Kg + base))[i];
        ((float4*)Vs)[i] = ((const float4*)(Vg + base))[i];
    }
    for (int i = tid; i < 1024; i += 256) zs[i] = zero_mask[b * LL + i];
    __syncthreads();

    const float scale = 0.35355339059327373f;
    int q = part * 256 + tid;      // one query per thread
    int tq = q >> 6, vq = q & 63;

    float4 q0 = ((const float4*)(Qg + base + q * 8))[0];
    float4 q1 = ((const float4*)(Qg + base + q * 8))[1];
    q0.x *= scale; q0.y *= scale; q0.z *= scale; q0.w *= scale;
    q1.x *= scale; q1.y *= scale; q1.z *= scale; q1.w *= scale;

    float ssum = 0.0f;
    float4 a0 = make_float4(0, 0, 0, 0), a1 = make_float4(0, 0, 0, 0);

    // same-time block: 64 keys
    int kb = tq << 6;
#pragma unroll 4
    for (int j = 0; j < 64; j++) {
        int k = kb + j;
        const float4* K4 = (const float4*)(Ks + k * 8);
        float4 k0 = K4[0], k1 = K4[1];
        float dot = q0.x * k0.x + q0.y * k0.y + q0.z * k0.z + q0.w * k0.w +
                    q1.x * k1.x + q1.y * k1.y + q1.z * k1.z + q1.w * k1.w;
        float wgt = __expf(dot);
        wgt = zs[k] ? 0.0f : wgt;
        ssum += wgt;
        const float4* V4 = (const float4*)(Vs + k * 8);
        float4 v0 = V4[0], v1 = V4[1];
        a0.x += wgt * v0.x; a0.y += wgt * v0.y; a0.z += wgt * v0.z; a0.w += wgt * v0.w;
        a1.x += wgt * v1.x; a1.y += wgt * v1.y; a1.z += wgt * v1.z; a1.w += wgt * v1.w;
    }
    // same-type column: 15 keys
#pragma unroll
    for (int t = 0; t < 16; t++) {
        if (t == tq) continue;
        int k = (t << 6) + vq;
        const float4* K4 = (const float4*)(Ks + k * 8);
        float4 k0 = K4[0], k1 = K4[1];
        float dot = q0.x * k0.x + q0.y * k0.y + q0.z * k0.z + q0.w * k0.w +
                    q1.x * k1.x + q1.y * k1.y + q1.z * k1.z + q1.w * k1.w;
        float wgt = __expf(dot);
        wgt = zs[k] ? 0.0f : wgt;
        ssum += wgt;
        const float4* V4 = (const float4*)(Vs + k * 8);
        float4 v0 = V4[0], v1 = V4[1];
        a0.x += wgt * v0.x; a0.y += wgt * v0.y; a0.z += wgt * v0.z; a0.w += wgt * v0.w;
        a1.x += wgt * v1.x; a1.y += wgt * v1.y; a1.z += wgt * v1.z; a1.w += wgt * v1.w;
    }

    float inv = 1.0f / ssum;
    __half* o = out + ((size_t)(b * LL + q)) * EE + h * 8;
    uint4 pk;
    pk.x = pack2h(a0.x * inv, a0.y * inv);
    pk.y = pack2h(a0.z * inv, a0.w * inv);
    pk.z = pack2h(a1.x * inv, a1.y * inv);
    pk.w = pack2h(a1.z * inv, a1.w * inv);
    *(uint4*)o = pk;
}

// ---------------- Wo projection + residual + LN1 (fp16 GEMM) ----------------
__global__ __launch_bounds__(256) void gemm_wo_ln(const __half* __restrict__ A,
                                                  const __half* __restrict__ WT,
                                                  const float* __restrict__ bias,
                                                  float* __restrict__ x,
                                                  __half* __restrict__ xh,
                                                  const float* __restrict__ ln_s,
                                                  const float* __restrict__ ln_b)
{
    __shared__ __align__(16) __half As[64 * SPH];
    __shared__ __align__(16) __half Ws[64 * SPH];
    __shared__ float buf[64 * 65];

    int tid = threadIdx.x;
    int w = tid >> 5, lane = tid & 31;
    int wm = w >> 1, wn = w & 1;
    int rm = wm * 16, cn = wn * 32;
    int row0 = blockIdx.x * 64;
    int gr = lane >> 2, gc = (lane & 3) * 2;

    for (int i = tid; i < 512; i += 256) {
        int r = i >> 3, seg = i & 7;
        *(uint4*)&As[r * SPH + seg * 8] = *(const uint4*)&A[(size_t)(row0 + r) * 64 + seg * 8];
    }
    for (int i = tid; i < 512; i += 256) {
        int n = i >> 3, seg = i & 7;
        *(uint4*)&Ws[n * SPH + seg * 8] = *(const uint4*)&WT[n * 64 + seg * 8];
    }
    __syncthreads();

    float acc[4][4];
#pragma unroll
    for (int j = 0; j < 4; j++)
#pragma unroll
        for (int r = 0; r < 4; r++) acc[j][r] = 0.0f;

#pragma unroll
    for (int kt = 0; kt < 4; kt++) {
        int kk = kt * 16;
        unsigned a[4], b[4][2];
        a[0] = *(unsigned*)&As[(rm + gr) * SPH + kk + gc];
        a[1] = *(unsigned*)&As[(rm + gr + 8) * SPH + kk + gc];
        a[2] = *(unsigned*)&As[(rm + gr) * SPH + kk + gc + 8];
        a[3] = *(unsigned*)&As[(rm + gr + 8) * SPH + kk + gc + 8];
#pragma unroll
        for (int ni = 0; ni < 4; ni++) {
            int n = cn + ni * 8 + gr;
            b[ni][0] = *(unsigned*)&Ws[n * SPH + kk + gc];
            b[ni][1] = *(unsigned*)&Ws[n * SPH + kk + gc + 8];
        }
#pragma unroll
        for (int ni = 0; ni < 4; ni++) mma_f16(acc[ni], a, b[ni]);
    }

#pragma unroll
    for (int ni = 0; ni < 4; ni++) {
        int c = cn + ni * 8 + gc;
        float b0 = bias[c], b1v = bias[c + 1];
        buf[(rm + gr) * 65 + c] = acc[ni][0] + b0;
        buf[(rm + gr) * 65 + c + 1] = acc[ni][1] + b1v;
        buf[(rm + gr + 8) * 65 + c] = acc[ni][2] + b0;
        buf[(rm + gr + 8) * 65 + c + 1] = acc[ni][3] + b1v;
    }
    __syncthreads();

    for (int rr = 0; rr < 8; rr++) {
        int row = w * 8 + rr;
        size_t go = (size_t)(row0 + row) * 64;
        float y0 = buf[row * 65 + lane] + x[go + lane];
        float y1 = buf[row * 65 + lane + 32] + x[go + lane + 32];
        float mean = warp_sum32(y0 + y1) * (1.0f / 64.0f);
        float d0 = y0 - mean, d1 = y1 - mean;
        float var = warp_sum32(d0 * d0 + d1 * d1) * (1.0f / 64.0f);
        float inv = rsqrtf(var + 1e-5f);
        float o0 = d0 * inv * ln_s[lane] + ln_b[lane];
        float o1 = d1 * inv * ln_s[lane + 32] + ln_b[lane + 32];
        x[go + lane] = o0;
        x[go + lane + 32] = o1;
        xh[go + lane] = __float2half_rn(o0);
        xh[go + lane + 32] = __float2half_rn(o1);
    }
}

// ---------------- fused FFN (fp16), 128 rows/block, cp.async double-buffered ----------------
// smem layout (bytes):
//   XS:   0      .. 18432   (128 rows * 144B)
//   HS:   18432  .. 36864
//   WS:   36864  .. 73728   (2 stages * (W1s 9216 + W2s 9216))
//   buf:  aliases WS (128*65*4 = 33280 <= 36864), used after chunk loop
#define XS_OFF 0
#define HS_OFF 18432
#define WS_OFF 36864
#define WS_STRIDE 18432
#define FBUF_OFF 36864
#define FFN_SMEM 73728

__global__ __launch_bounds__(512) void ffn_fused(const float* __restrict__ xin,
                                                 const __half* __restrict__ xinh,
                                                 const __half* __restrict__ w1T,
                                                 const __half* __restrict__ w2T,
                                                 const float* __restrict__ b1,
                                                 const float* __restrict__ b2,
                                                 float* __restrict__ x,
                                                 __half* __restrict__ xh,
                                                 const float* __restrict__ ln_s,
                                                 const float* __restrict__ ln_b)
{
    extern __shared__ __align__(16) char sm[];
    __half* XS = (__half*)(sm + XS_OFF);
    __half* HS = (__half*)(sm + HS_OFF);
    float* buf = (float*)(sm + FBUF_OFF);
    unsigned smem_base = (unsigned)__cvta_generic_to_shared(sm);

    int tid = threadIdx.x;
    int w = tid >> 5, lane = tid & 31;
    int wm = w >> 1, wn = w & 1;
    int rm = wm * 16, cn = wn * 32;
    int row0 = blockIdx.x * 128;
    int gr = lane >> 2, gc = (lane & 3) * 2;

    // X tile: 128 rows x 64 halves via cp.async (2 x 16B per thread)
    {
        unsigned xs = smem_base + XS_OFF;
        int r = tid >> 2, seg0 = (tid & 3) * 2;
        const __half* src = xinh + (size_t)(row0 + r) * 64;
        CP_ASYNC16(xs + r * 144 + seg0 * 16, src + seg0 * 8);
        CP_ASYNC16(xs + r * 144 + (seg0 + 1) * 16, src + (seg0 + 1) * 8);
    }

    // weight loader indices (512 threads = 64 rows x 8 segs)
    int wr = tid >> 3, wseg = tid & 7;
    unsigned wdst = (unsigned)(wr * 144 + wseg * 16);
    int wsrc = wr * 64 + wseg * 8;

    float acc2[4][4];
#pragma unroll
    for (int j = 0; j < 4; j++)
#pragma unroll
        for (int r = 0; r < 4; r++) acc2[j][r] = 0.0f;

    // preload chunk 0 into stage 0
    {
        unsigned st = smem_base + WS_OFF;
        CP_ASYNC16(st + wdst, w1T + wsrc);
        CP_ASYNC16(st + 9216 + wdst, w2T + wsrc);
    }
    CP_COMMIT();

    for (int c = 0; c < 32; c++) {
        int s = c & 1;
        if (c + 1 < 32) {
            unsigned st = smem_base + WS_OFF + (s ^ 1) * WS_STRIDE;
            int src = (c + 1) * 4096 + wsrc;
            CP_ASYNC16(st + wdst, w1T + src);
            CP_ASYNC16(st + 9216 + wdst, w2T + src);
        }
        CP_COMMIT();
        CP_WAIT1();
        __syncthreads();

        __half* W1s = (__half*)(sm + WS_OFF + s * WS_STRIDE);
        __half* W2s = (__half*)(sm + WS_OFF + s * WS_STRIDE + 9216);

        // GEMM1: h = relu(x @ W1c + b1c), warp tile 16x32
        float hacc[4][4];
#pragma unroll
        for (int j = 0; j < 4; j++)
#pragma unroll
            for (int r = 0; r < 4; r++) hacc[j][r] = 0.0f;

#pragma unroll
        for (int kt = 0; kt < 4; kt++) {
            int kk = kt * 16;
            unsigned a[4], b[4][2];
            a[0] = *(unsigned*)&XS[(rm + gr) * SPH + kk + gc];
            a[1] = *(unsigned*)&XS[(rm + gr + 8) * SPH + kk + gc];
            a[2] = *(unsigned*)&XS[(rm + gr) * SPH + kk + gc + 8];
            a[3] = *(unsigned*)&XS[(rm + gr + 8) * SPH + kk + gc + 8];
#pragma unroll
            for (int ni = 0; ni < 4; ni++) {
                int n = cn + ni * 8 + gr;
                b[ni][0] = *(unsigned*)&W1s[n * SPH + kk + gc];
                b[ni][1] = *(unsigned*)&W1s[n * SPH + kk + gc + 8];
            }
#pragma unroll
            for (int ni = 0; ni < 4; ni++) mma_f16(hacc[ni], a, b[ni]);
        }

#pragma unroll
        for (int ni = 0; ni < 4; ni++) {
            int cl = cn + ni * 8 + gc;
            int cg = c * 64 + cl;
            float bb0 = b1[cg], bb1 = b1[cg + 1];
            float v0 = fmaxf(hacc[ni][0] + bb0, 0.0f);
            float v1 = fmaxf(hacc[ni][1] + bb1, 0.0f);
            float v2 = fmaxf(hacc[ni][2] + bb0, 0.0f);
            float v3 = fmaxf(hacc[ni][3] + bb1, 0.0f);
            *(unsigned*)&HS[(rm + gr) * SPH + cl] = pack2h(v0, v1);
            *(unsigned*)&HS[(rm + gr + 8) * SPH + cl] = pack2h(v2, v3);
        }
        __syncthreads();

        // GEMM2: acc2 += h @ W2c
#pragma unroll
        for (int kt = 0; kt < 4; kt++) {
            int kk = kt * 16;
            unsigned a[4], b[4][2];
            a[0] = *(unsigned*)&HS[(rm + gr) * SPH + kk + gc];
            a[1] = *(unsigned*)&HS[(rm + gr + 8) * SPH + kk + gc];
            a[2] = *(unsigned*)&HS[(rm + gr) * SPH + kk + gc + 8];
            a[3] = *(unsigned*)&HS[(rm + gr + 8) * SPH + kk + gc + 8];
#pragma unroll
            for (int ni = 0; ni < 4; ni++) {
                int n = cn + ni * 8 + gr;
                b[ni][0] = *(unsigned*)&W2s[n * SPH + kk + gc];
                b[ni][1] = *(unsigned*)&W2s[n * SPH + kk + gc + 8];
            }
#pragma unroll
            for (int ni = 0; ni < 4; ni++) mma_f16(acc2[ni], a, b[ni]);
        }
        __syncthreads();
    }

    // epilogue: + b2 -> buf, + residual, LN2
#pragma unroll
    for (int ni = 0; ni < 4; ni++) {
        int cc = cn + ni * 8 + gc;
        float b0 = b2[cc], b1v = b2[cc + 1];
        buf[(rm + gr) * 65 + cc] = acc2[ni][0] + b0;
        buf[(rm + gr) * 65 + cc + 1] = acc2[ni][1] + b1v;
        buf[(rm + gr + 8) * 65 + cc] = acc2[ni][2] + b0;
        buf[(rm + gr + 8) * 65 + cc + 1] = acc2[ni][3] + b1v;
    }
    __syncthreads();

    for (int rr = 0; rr < 8; rr++) {
        int row = w * 8 + rr;      // 16 warps x 8 rows = 128
        size_t go = (size_t)(row0 + row) * 64;
        float y0 = buf[row * 65 + lane] + xin[go + lane];
        float y1 = buf[row * 65 + lane + 32] + xin[go + lane + 32];
        float mean = warp_sum32(y0 + y1) * (1.0f / 64.0f);
        float d0 = y0 - mean, d1 = y1 - mean;
        float var = warp_sum32(d0 * d0 + d1 * d1) * (1.0f / 64.0f);
        float inv = rsqrtf(var + 1e-5f);
        float o0 = d0 * inv * ln_s[lane] + ln_b[lane];
        float o1 = d1 * inv * ln_s[lane + 32] + ln_b[lane + 32];
        x[go + lane] = o0;
        x[go + lane + 32] = o1;
        xh[go + lane] = __float2half_rn(o0);
        xh[go + lane + 32] = __float2half_rn(o1);
    }
}

// ---------------- head ----------------
__global__ void head_kernel(const float* __restrict__ x,
                            const float* __restrict__ W_head,
                            const float* __restrict__ b_head,
                            float* __restrict__ out)
{
    int b = blockIdx.x;
    int tid = threadIdx.x;  // 192
    int v = tid / 3, c = tid % 3;
    const float* row = x + ((size_t)(b * LL + (SS - 1) * VV + v)) * EE;
    float acc = b_head[c];
#pragma unroll
    for (int e = 0; e < EE; e++) acc += row[e] * W_head[e * 3 + c];
    out[b * (VV * 3) + tid] = acc;
}

// ---------------- launch ----------------
extern "C" void kernel_launch(void* const* d_in, const int* in_sizes, int n_in,
                              void* d_out, int out_size)
{
    const float* features    = (const float*)d_in[0];
    const int*   overlap_tag = (const int*)d_in[1];
    const int*   poi_id      = (const int*)d_in[2];
    const float* W_raw       = (const float*)d_in[3];
    const float* b_raw       = (const float*)d_in[4];
    const float* pos_tab     = (const float*)d_in[5];
    const float* type_tab    = (const float*)d_in[6];
    const float* poi_tab     = (const float*)d_in[7];
    const float* overlap_tab = (const float*)d_in[8];
    const float* W_comb      = (const float*)d_in[9];
    const float* b_comb      = (const float*)d_in[10];
    const float* Wqkv        = (const float*)d_in[11];
    const float* bqkv        = (const float*)d_in[12];
    const float* Wo          = (const float*)d_in[13];
    const float* bo          = (const float*)d_in[14];
    const float* ln1_s       = (const float*)d_in[15];
    const float* ln1_b       = (const float*)d_in[16];
    const float* W1          = (const float*)d_in[17];
    const float* b1          = (const float*)d_in[18];
    const float* W2          = (const float*)d_in[19];
    const float* b2          = (const float*)d_in[20];
    const float* ln2_s       = (const float*)d_in[21];
    const float* ln2_b       = (const float*)d_in[22];
    const float* W_head      = (const float*)d_in[23];
    const float* b_head      = (const float*)d_in[24];
    float* out = (float*)d_out;

    float *x, *qb, *kb, *vb;
    __half *xh, *attnh, *qkvT, *woT, *w1T, *w2T;
    unsigned char* zero;
    cudaGetSymbolAddress((void**)&x,     g_x);
    cudaGetSymbolAddress((void**)&xh,    g_xh);
    cudaGetSymbolAddress((void**)&qb,    g_q);
    cudaGetSymbolAddress((void**)&kb,    g_k);
    cudaGetSymbolAddress((void**)&vb,    g_v);
    cudaGetSymbolAddress((void**)&attnh, g_attnh);
    cudaGetSymbolAddress((void**)&zero,  g_zero);
    cudaGetSymbolAddress((void**)&qkvT,  g_qkvT);
    cudaGetSymbolAddress((void**)&woT,   g_woT);
    cudaGetSymbolAddress((void**)&w1T,   g_w1T);
    cudaGetSymbolAddress((void**)&w2T,   g_w2T);

    const int ATTN_SMEM = 16384 * 4 + 1024;
    cudaFuncSetAttribute(attn_kernel, cudaFuncAttributeMaxDynamicSharedMemorySize, ATTN_SMEM);
    cudaFuncSetAttribute(ffn_fused, cudaFuncAttributeMaxDynamicSharedMemorySize, FFN_SMEM);

    prep_weights<<<dim3(2048, 4), 256>>>(Wqkv, Wo, W1, W2);

    embed_kernel<<<ML, 64>>>(features, overlap_tag, poi_id, W_raw, b_raw,
                             pos_tab, type_tab, poi_tab, overlap_tab,
                             W_comb, b_comb, x, xh, zero);

    for (int l = 0; l < NL; l++) {
        gemm_qkv<<<dim3(3, ML / 128), 256>>>(
            xh, qkvT + l * 12288, bqkv + l * 192, qb, kb, vb);
        attn_kernel<<<BB * HH * 4, 256, ATTN_SMEM>>>(qb, kb, vb, zero, attnh);
        gemm_wo_ln<<<ML / 64, 256>>>(
            attnh, woT + l * 4096, bo + l * EE, x, xh,
            ln1_s + l * EE, ln1_b + l * EE);
        ffn_fused<<<ML / 128, 512, FFN_SMEM>>>(
            x, xh, w1T + l * DFF * 64, w2T + l * DFF * 64,
            b1 + l * DFF, b2 + l * EE, x, xh,
            ln2_s + l * EE, ln2_b + l * EE);
    }

    head_kernel<<<BB, VV * 3>>>(x, W_head, b_head, out);
}

// round 6
// speedup vs baseline: 7.5877x; 1.4914x over previous
#include <cuda_runtime.h>
#include <cuda_fp16.h>
#include <math.h>

#define BB 16
#define SS 16
#define VV 64
#define EE 64
#define HH 8
#define NL 4
#define DFF 2048
#define LL 1024
#define ML (BB*LL)
#define SPH 72   // smem row stride in halves (64 data + 8 pad) = 144 bytes

// ---------------- scratch ----------------
__device__ float g_x[ML * EE];            // fp32 residual stream
__device__ __half g_xh[ML * EE];          // fp16 copy of x
__device__ float g_q[ML * EE];
__device__ float g_k[ML * EE];
__device__ float g_v[ML * EE];
__device__ __half g_attnh[ML * EE];       // attention output (fp16)
__device__ unsigned char g_zero[ML];

// pre-converted transposed fp16 weights ([n][k])
__device__ __align__(256) __half g_qkvT[NL * 192 * 64];
__device__ __align__(256) __half g_woT[NL * 64 * 64];
__device__ __align__(256) __half g_w1T[NL * DFF * 64];
__device__ __align__(256) __half g_w2T[NL * DFF * 64];

// ---------------- helpers ----------------
__device__ __forceinline__ unsigned pack2h(float a, float b) {
    __half2 h = __floats2half2_rn(a, b);
    return *(unsigned*)&h;
}
__device__ __forceinline__ void mma_f16(float* c, const unsigned* a, const unsigned* b) {
    asm volatile(
        "mma.sync.aligned.m16n8k16.row.col.f32.f16.f16.f32 "
        "{%0,%1,%2,%3}, {%4,%5,%6,%7}, {%8,%9}, {%0,%1,%2,%3};\n"
        : "+f"(c[0]), "+f"(c[1]), "+f"(c[2]), "+f"(c[3])
        : "r"(a[0]), "r"(a[1]), "r"(a[2]), "r"(a[3]), "r"(b[0]), "r"(b[1]));
}
__device__ __forceinline__ float warp_sum32(float v) {
#pragma unroll
    for (int o = 16; o > 0; o >>= 1) v += __shfl_xor_sync(0xffffffffu, v, o);
    return v;
}
#define CP_ASYNC16(dst, src) \
    asm volatile("cp.async.ca.shared.global [%0], [%1], 16;\n" :: "r"(dst), "l"(src))
#define CP_COMMIT() asm volatile("cp.async.commit_group;\n")
#define CP_WAIT1()  asm volatile("cp.async.wait_group 1;\n")

// ---------------- weight prep ----------------
__global__ void prep_weights(const float* __restrict__ Wqkv,
                             const float* __restrict__ Wo,
                             const float* __restrict__ W1,
                             const float* __restrict__ W2)
{
    int t = blockIdx.x * 256 + threadIdx.x;
    int which = blockIdx.y;
    if (which == 0) {                       // qkv: [64k][192n] -> [n][k]
        if (t >= NL * 12288) return;
        int layer = t / 12288, rem = t % 12288, n = rem >> 6, k = rem & 63;
        g_qkvT[t] = __float2half_rn(Wqkv[(size_t)layer * 12288 + k * 192 + n]);
    } else if (which == 1) {                // wo: [64k][64n] -> [n][k]
        if (t >= NL * 4096) return;
        int layer = t / 4096, rem = t % 4096, n = rem >> 6, k = rem & 63;
        g_woT[t] = __float2half_rn(Wo[(size_t)layer * 4096 + k * 64 + n]);
    } else if (which == 2) {                // w1: [64k][2048n] -> [c][n][k]
        if (t >= NL * DFF * 64) return;
        int layer = t / (DFF * 64), rem = t % (DFF * 64), n = rem >> 6, k = rem & 63;
        g_w1T[t] = __float2half_rn(W1[(size_t)layer * DFF * 64 + k * DFF + n]);
    } else {                                // w2: [2048k][64n] -> [c][n][kl]
        if (t >= NL * DFF * 64) return;
        int layer = t / (DFF * 64), rem = t % (DFF * 64);
        int c = rem / 4096, w = rem % 4096, n = w >> 6, kl = w & 63;
        g_w2T[t] = __float2half_rn(W2[(size_t)layer * DFF * 64 + (c * 64 + kl) * 64 + n]);
    }
}

// ---------------- embed ----------------
__global__ void embed_kernel(const float* __restrict__ features,
                             const int* __restrict__ overlap_tag,
                             const int* __restrict__ poi_id,
                             const float* __restrict__ W_raw,
                             const float* __restrict__ b_raw,
                             const float* __restrict__ pos_tab,
                             const float* __restrict__ type_tab,
                             const float* __restrict__ poi_tab,
                             const float* __restrict__ overlap_tab,
                             const float* __restrict__ W_comb,
                             const float* __restrict__ b_comb,
                             float* __restrict__ x,
                             __half* __restrict__ xh,
                             unsigned char* __restrict__ zero_mask)
{
    int bl = blockIdx.x;
    int l  = bl & (LL - 1);
    int s  = l >> 6;
    int v  = l & 63;
    int tid = threadIdx.x;  // 64

    __shared__ float concat[80];
    const float* f = features + (size_t)bl * 3;
    float f0 = f[0], f1 = f[1], f2 = f[2];

    concat[tid] = f0 * W_raw[tid] + f1 * W_raw[64 + tid] + f2 * W_raw[128 + tid] + b_raw[tid];
    if (tid < 8) {
        int ov = overlap_tag[bl];
        concat[64 + tid] = (ov == 0) ? 0.0f : overlap_tab[ov * 8 + tid];
        int poi = poi_id[bl];
        concat[72 + tid] = (poi == 0) ? 0.0f : poi_tab[poi * 8 + tid];
    }
    if (tid == 0) zero_mask[bl] = (f0 + f1 + f2 == 0.0f) ? 1 : 0;
    __syncthreads();

    float acc = b_comb[tid];
#pragma unroll
    for (int j = 0; j < 80; j++) acc += concat[j] * W_comb[j * EE + tid];
    acc += pos_tab[s * EE + tid] + type_tab[v * EE + tid];
    x[(size_t)bl * EE + tid] = acc;
    xh[(size_t)bl * EE + tid] = __float2half_rn(acc);
}

// ---------------- QKV GEMM (fp16): xh[128,64] @ WT-chunk -> permuted fp32 [B][H][L][8] ----------------
__global__ __launch_bounds__(256) void gemm_qkv(const __half* __restrict__ Xh,
                                                const __half* __restrict__ WT,
                                                const float* __restrict__ bias,
                                                float* __restrict__ Qo,
                                                float* __restrict__ Ko,
                                                float* __restrict__ Vo)
{
    __shared__ __align__(16) __half As[128 * SPH];
    __shared__ __align__(16) __half Ws[64 * SPH];

    int tid = threadIdx.x;
    int w = tid >> 5, lane = tid & 31;
    int wm = w >> 1, wn = w & 1;
    int rm = wm * 32, cn = wn * 32;
    int row0 = blockIdx.y * 128;
    int sel = blockIdx.x;
    int gr = lane >> 2, gc = (lane & 3) * 2;

    for (int i = tid; i < 1024; i += 256) {
        int r = i >> 3, seg = i & 7;
        *(uint4*)&As[r * SPH + seg * 8] = *(const uint4*)&Xh[(size_t)(row0 + r) * 64 + seg * 8];
    }
    const __half* src = WT + sel * 4096;
    for (int i = tid; i < 512; i += 256) {
        int n = i >> 3, seg = i & 7;
        *(uint4*)&Ws[n * SPH + seg * 8] = *(const uint4*)&src[n * 64 + seg * 8];
    }
    __syncthreads();

    float acc[2][4][4];
#pragma unroll
    for (int i = 0; i < 2; i++)
#pragma unroll
        for (int j = 0; j < 4; j++)
#pragma unroll
            for (int r = 0; r < 4; r++) acc[i][j][r] = 0.0f;

#pragma unroll
    for (int kt = 0; kt < 4; kt++) {
        int kk = kt * 16;
        unsigned a[2][4], b[4][2];
#pragma unroll
        for (int mi = 0; mi < 2; mi++) {
            int r = rm + mi * 16;
            a[mi][0] = *(unsigned*)&As[(r + gr) * SPH + kk + gc];
            a[mi][1] = *(unsigned*)&As[(r + gr + 8) * SPH + kk + gc];
            a[mi][2] = *(unsigned*)&As[(r + gr) * SPH + kk + gc + 8];
            a[mi][3] = *(unsigned*)&As[(r + gr + 8) * SPH + kk + gc + 8];
        }
#pragma unroll
        for (int ni = 0; ni < 4; ni++) {
            int n = cn + ni * 8 + gr;
            b[ni][0] = *(unsigned*)&Ws[n * SPH + kk + gc];
            b[ni][1] = *(unsigned*)&Ws[n * SPH + kk + gc + 8];
        }
#pragma unroll
        for (int mi = 0; mi < 2; mi++)
#pragma unroll
            for (int ni = 0; ni < 4; ni++)
                mma_f16(acc[mi][ni], a[mi], b[ni]);
    }

    int b = row0 >> 10;
    float* outp = (sel == 0) ? Qo : ((sel == 1) ? Ko : Vo);
#pragma unroll
    for (int mi = 0; mi < 2; mi++) {
        int r0 = rm + mi * 16 + gr;
        int l0 = (row0 + r0) & (LL - 1);
#pragma unroll
        for (int ni = 0; ni < 4; ni++) {
            int loc = cn + ni * 8 + gc;
            int h = loc >> 3, d = loc & 7;
            float b0 = bias[sel * 64 + loc], b1v = bias[sel * 64 + loc + 1];
            size_t base = ((size_t)(b * 8 + h) * LL);
            *(float2*)&outp[(base + l0) * 8 + d] =
                make_float2(acc[mi][ni][0] + b0, acc[mi][ni][1] + b1v);
            *(float2*)&outp[(base + l0 + 8) * 8 + d] =
                make_float2(acc[mi][ni][2] + b0, acc[mi][ni][3] + b1v);
        }
    }
}

// ---------------- attention: one block per (b,h), 2 adjacent queries/thread ----------------
__global__ __launch_bounds__(512) void attn_kernel(const float* __restrict__ Qg,
                                                   const float* __restrict__ Kg,
                                                   const float* __restrict__ Vg,
                                                   const unsigned char* __restrict__ zero_mask,
                                                   __half* __restrict__ out)
{
    extern __shared__ float smf[];
    float* Ks = smf;                      // [1024*8]
    float* Vs = smf + 8192;               // [1024*8]
    unsigned char* zs = (unsigned char*)(smf + 16384);

    int bh = blockIdx.x;                  // 128 blocks
    int b = bh >> 3, h = bh & 7;
    int tid = threadIdx.x;                // 512
    size_t base = (size_t)bh * LL * 8;

    for (int i = tid; i < 2048; i += 512) {
        ((float4*)Ks)[i] = ((const float4*)(Kg + base))[i];
        ((float4*)Vs)[i] = ((const float4*)(Vg + base))[i];
    }
    for (int i = tid; i < 1024; i += 512) zs[i] = zero_mask[b * LL + i];
    __syncthreads();

    const float scale = 0.35355339059327373f;
    int q0 = tid * 2, q1 = q0 + 1;        // same t-block
    int tq = q0 >> 6;
    int vq0 = q0 & 63, vq1 = vq0 + 1;

    float4 qa0 = ((const float4*)(Qg + base + q0 * 8))[0];
    float4 qa1 = ((const float4*)(Qg + base + q0 * 8))[1];
    float4 qb0 = ((const float4*)(Qg + base + q1 * 8))[0];
    float4 qb1 = ((const float4*)(Qg + base + q1 * 8))[1];
    qa0.x *= scale; qa0.y *= scale; qa0.z *= scale; qa0.w *= scale;
    qa1.x *= scale; qa1.y *= scale; qa1.z *= scale; qa1.w *= scale;
    qb0.x *= scale; qb0.y *= scale; qb0.z *= scale; qb0.w *= scale;
    qb1.x *= scale; qb1.y *= scale; qb1.z *= scale; qb1.w *= scale;

    float sA = 0.0f, sB = 0.0f;
    float4 accA0 = make_float4(0, 0, 0, 0), accA1 = make_float4(0, 0, 0, 0);
    float4 accB0 = make_float4(0, 0, 0, 0), accB1 = make_float4(0, 0, 0, 0);

    // block-diagonal part: 64 shared keys for both queries
    int kb = tq << 6;
#pragma unroll 4
    for (int j = 0; j < 64; j++) {
        int k = kb + j;
        const float4* K4 = (const float4*)(Ks + k * 8);
        float4 k0 = K4[0], k1 = K4[1];
        float dA = qa0.x * k0.x + qa0.y * k0.y + qa0.z * k0.z + qa0.w * k0.w +
                   qa1.x * k1.x + qa1.y * k1.y + qa1.z * k1.z + qa1.w * k1.w;
        float dB = qb0.x * k0.x + qb0.y * k0.y + qb0.z * k0.z + qb0.w * k0.w +
                   qb1.x * k1.x + qb1.y * k1.y + qb1.z * k1.z + qb1.w * k1.w;
        float wA = __expf(dA), wB = __expf(dB);
        if (zs[k]) { wA = 0.0f; wB = 0.0f; }
        sA += wA; sB += wB;
        const float4* V4 = (const float4*)(Vs + k * 8);
        float4 v0 = V4[0], v1 = V4[1];
        accA0.x += wA * v0.x; accA0.y += wA * v0.y; accA0.z += wA * v0.z; accA0.w += wA * v0.w;
        accA1.x += wA * v1.x; accA1.y += wA * v1.y; accA1.z += wA * v1.z; accA1.w += wA * v1.w;
        accB0.x += wB * v0.x; accB0.y += wB * v0.y; accB0.z += wB * v0.z; accB0.w += wB * v0.w;
        accB1.x += wB * v1.x; accB1.y += wB * v1.y; accB1.z += wB * v1.z; accB1.w += wB * v1.w;
    }
    // same-type column for q0 (15 keys)
#pragma unroll
    for (int t = 0; t < 16; t++) {
        if (t == tq) continue;
        int k = (t << 6) + vq0;
        const float4* K4 = (const float4*)(Ks + k * 8);
        float4 k0 = K4[0], k1 = K4[1];
        float dA = qa0.x * k0.x + qa0.y * k0.y + qa0.z * k0.z + qa0.w * k0.w +
                   qa1.x * k1.x + qa1.y * k1.y + qa1.z * k1.z + qa1.w * k1.w;
        float wA = __expf(dA);
        wA = zs[k] ? 0.0f : wA;
        sA += wA;
        const float4* V4 = (const float4*)(Vs + k * 8);
        float4 v0 = V4[0], v1 = V4[1];
        accA0.x += wA * v0.x; accA0.y += wA * v0.y; accA0.z += wA * v0.z; accA0.w += wA * v0.w;
        accA1.x += wA * v1.x; accA1.y += wA * v1.y; accA1.z += wA * v1.z; accA1.w += wA * v1.w;
    }
    // same-type column for q1 (15 keys)
#pragma unroll
    for (int t = 0; t < 16; t++) {
        if (t == tq) continue;
        int k = (t << 6) + vq1;
        const float4* K4 = (const float4*)(Ks + k * 8);
        float4 k0 = K4[0], k1 = K4[1];
        float dB = qb0.x * k0.x + qb0.y * k0.y + qb0.z * k0.z + qb0.w * k0.w +
                   qb1.x * k1.x + qb1.y * k1.y + qb1.z * k1.z + qb1.w * k1.w;
        float wB = __expf(dB);
        wB = zs[k] ? 0.0f : wB;
        sB += wB;
        const float4* V4 = (const float4*)(Vs + k * 8);
        float4 v0 = V4[0], v1 = V4[1];
        accB0.x += wB * v0.x; accB0.y += wB * v0.y; accB0.z += wB * v0.z; accB0.w += wB * v0.w;
        accB1.x += wB * v1.x; accB1.y += wB * v1.y; accB1.z += wB * v1.z; accB1.w += wB * v1.w;
    }

    float invA = 1.0f / sA, invB = 1.0f / sB;
    __half* oA = out + ((size_t)(b * LL + q0)) * EE + h * 8;
    uint4 pk;
    pk.x = pack2h(accA0.x * invA, accA0.y * invA);
    pk.y = pack2h(accA0.z * invA, accA0.w * invA);
    pk.z = pack2h(accA1.x * invA, accA1.y * invA);
    pk.w = pack2h(accA1.z * invA, accA1.w * invA);
    *(uint4*)oA = pk;
    __half* oB = out + ((size_t)(b * LL + q1)) * EE + h * 8;
    pk.x = pack2h(accB0.x * invB, accB0.y * invB);
    pk.y = pack2h(accB0.z * invB, accB0.w * invB);
    pk.z = pack2h(accB1.x * invB, accB1.y * invB);
    pk.w = pack2h(accB1.z * invB, accB1.w * invB);
    *(uint4*)oB = pk;
}

// ---------------- Wo projection + residual + LN1 (fp16 GEMM) ----------------
__global__ __launch_bounds__(256) void gemm_wo_ln(const __half* __restrict__ A,
                                                  const __half* __restrict__ WT,
                                                  const float* __restrict__ bias,
                                                  float* __restrict__ x,
                                                  __half* __restrict__ xh,
                                                  const float* __restrict__ ln_s,
                                                  const float* __restrict__ ln_b)
{
    __shared__ __align__(16) __half As[64 * SPH];
    __shared__ __align__(16) __half Ws[64 * SPH];
    __shared__ float buf[64 * 65];

    int tid = threadIdx.x;
    int w = tid >> 5, lane = tid & 31;
    int wm = w >> 1, wn = w & 1;
    int rm = wm * 16, cn = wn * 32;
    int row0 = blockIdx.x * 64;
    int gr = lane >> 2, gc = (lane & 3) * 2;

    for (int i = tid; i < 512; i += 256) {
        int r = i >> 3, seg = i & 7;
        *(uint4*)&As[r * SPH + seg * 8] = *(const uint4*)&A[(size_t)(row0 + r) * 64 + seg * 8];
    }
    for (int i = tid; i < 512; i += 256) {
        int n = i >> 3, seg = i & 7;
        *(uint4*)&Ws[n * SPH + seg * 8] = *(const uint4*)&WT[n * 64 + seg * 8];
    }
    __syncthreads();

    float acc[4][4];
#pragma unroll
    for (int j = 0; j < 4; j++)
#pragma unroll
        for (int r = 0; r < 4; r++) acc[j][r] = 0.0f;

#pragma unroll
    for (int kt = 0; kt < 4; kt++) {
        int kk = kt * 16;
        unsigned a[4], b[4][2];
        a[0] = *(unsigned*)&As[(rm + gr) * SPH + kk + gc];
        a[1] = *(unsigned*)&As[(rm + gr + 8) * SPH + kk + gc];
        a[2] = *(unsigned*)&As[(rm + gr) * SPH + kk + gc + 8];
        a[3] = *(unsigned*)&As[(rm + gr + 8) * SPH + kk + gc + 8];
#pragma unroll
        for (int ni = 0; ni < 4; ni++) {
            int n = cn + ni * 8 + gr;
            b[ni][0] = *(unsigned*)&Ws[n * SPH + kk + gc];
            b[ni][1] = *(unsigned*)&Ws[n * SPH + kk + gc + 8];
        }
#pragma unroll
        for (int ni = 0; ni < 4; ni++) mma_f16(acc[ni], a, b[ni]);
    }

#pragma unroll
    for (int ni = 0; ni < 4; ni++) {
        int c = cn + ni * 8 + gc;
        float b0 = bias[c], b1v = bias[c + 1];
        buf[(rm + gr) * 65 + c] = acc[ni][0] + b0;
        buf[(rm + gr) * 65 + c + 1] = acc[ni][1] + b1v;
        buf[(rm + gr + 8) * 65 + c] = acc[ni][2] + b0;
        buf[(rm + gr + 8) * 65 + c + 1] = acc[ni][3] + b1v;
    }
    __syncthreads();

    for (int rr = 0; rr < 8; rr++) {
        int row = w * 8 + rr;
        size_t go = (size_t)(row0 + row) * 64;
        float y0 = buf[row * 65 + lane] + x[go + lane];
        float y1 = buf[row * 65 + lane + 32] + x[go + lane + 32];
        float mean = warp_sum32(y0 + y1) * (1.0f / 64.0f);
        float d0 = y0 - mean, d1 = y1 - mean;
        float var = warp_sum32(d0 * d0 + d1 * d1) * (1.0f / 64.0f);
        float inv = rsqrtf(var + 1e-5f);
        float o0 = d0 * inv * ln_s[lane] + ln_b[lane];
        float o1 = d1 * inv * ln_s[lane + 32] + ln_b[lane + 32];
        x[go + lane] = o0;
        x[go + lane + 32] = o1;
        xh[go + lane] = __float2half_rn(o0);
        xh[go + lane + 32] = __float2half_rn(o1);
    }
}

// ---------------- fused FFN (fp16), 128 rows/block, cp.async double-buffered ----------------
// smem layout (bytes):
//   XS:   0      .. 18432   (128 rows * 144B)
//   HS:   18432  .. 36864
//   WS:   36864  .. 73728   (2 stages * (W1s 9216 + W2s 9216))
//   buf:  aliases WS (128*65*4 = 33280 <= 36864), used after chunk loop
#define XS_OFF 0
#define HS_OFF 18432
#define WS_OFF 36864
#define WS_STRIDE 18432
#define FBUF_OFF 36864
#define FFN_SMEM 73728

__global__ __launch_bounds__(512) void ffn_fused(const float* __restrict__ xin,
                                                 const __half* __restrict__ xinh,
                                                 const __half* __restrict__ w1T,
                                                 const __half* __restrict__ w2T,
                                                 const float* __restrict__ b1,
                                                 const float* __restrict__ b2,
                                                 float* __restrict__ x,
                                                 __half* __restrict__ xh,
                                                 const float* __restrict__ ln_s,
                                                 const float* __restrict__ ln_b)
{
    extern __shared__ __align__(16) char sm[];
    __half* XS = (__half*)(sm + XS_OFF);
    __half* HS = (__half*)(sm + HS_OFF);
    float* buf = (float*)(sm + FBUF_OFF);
    unsigned smem_base = (unsigned)__cvta_generic_to_shared(sm);

    int tid = threadIdx.x;
    int w = tid >> 5, lane = tid & 31;
    int wm = w >> 1, wn = w & 1;
    int rm = wm * 16, cn = wn * 32;
    int row0 = blockIdx.x * 128;
    int gr = lane >> 2, gc = (lane & 3) * 2;

    // X tile: 128 rows x 64 halves via cp.async (2 x 16B per thread)
    {
        unsigned xs = smem_base + XS_OFF;
        int r = tid >> 2, seg0 = (tid & 3) * 2;
        const __half* src = xinh + (size_t)(row0 + r) * 64;
        CP_ASYNC16(xs + r * 144 + seg0 * 16, src + seg0 * 8);
        CP_ASYNC16(xs + r * 144 + (seg0 + 1) * 16, src + (seg0 + 1) * 8);
    }

    // weight loader indices (512 threads = 64 rows x 8 segs)
    int wr = tid >> 3, wseg = tid & 7;
    unsigned wdst = (unsigned)(wr * 144 + wseg * 16);
    int wsrc = wr * 64 + wseg * 8;

    float acc2[4][4];
#pragma unroll
    for (int j = 0; j < 4; j++)
#pragma unroll
        for (int r = 0; r < 4; r++) acc2[j][r] = 0.0f;

    // preload chunk 0 into stage 0
    {
        unsigned st = smem_base + WS_OFF;
        CP_ASYNC16(st + wdst, w1T + wsrc);
        CP_ASYNC16(st + 9216 + wdst, w2T + wsrc);
    }
    CP_COMMIT();

    for (int c = 0; c < 32; c++) {
        int s = c & 1;
        if (c + 1 < 32) {
            unsigned st = smem_base + WS_OFF + (s ^ 1) * WS_STRIDE;
            int src = (c + 1) * 4096 + wsrc;
            CP_ASYNC16(st + wdst, w1T + src);
            CP_ASYNC16(st + 9216 + wdst, w2T + src);
        }
        CP_COMMIT();
        CP_WAIT1();
        __syncthreads();

        __half* W1s = (__half*)(sm + WS_OFF + s * WS_STRIDE);
        __half* W2s = (__half*)(sm + WS_OFF + s * WS_STRIDE + 9216);

        // GEMM1: h = relu(x @ W1c + b1c), warp tile 16x32
        float hacc[4][4];
#pragma unroll
        for (int j = 0; j < 4; j++)
#pragma unroll
            for (int r = 0; r < 4; r++) hacc[j][r] = 0.0f;

#pragma unroll
        for (int kt = 0; kt < 4; kt++) {
            int kk = kt * 16;
            unsigned a[4], b[4][2];
            a[0] = *(unsigned*)&XS[(rm + gr) * SPH + kk + gc];
            a[1] = *(unsigned*)&XS[(rm + gr + 8) * SPH + kk + gc];
            a[2] = *(unsigned*)&XS[(rm + gr) * SPH + kk + gc + 8];
            a[3] = *(unsigned*)&XS[(rm + gr + 8) * SPH + kk + gc + 8];
#pragma unroll
            for (int ni = 0; ni < 4; ni++) {
                int n = cn + ni * 8 + gr;
                b[ni][0] = *(unsigned*)&W1s[n * SPH + kk + gc];
                b[ni][1] = *(unsigned*)&W1s[n * SPH + kk + gc + 8];
            }
#pragma unroll
            for (int ni = 0; ni < 4; ni++) mma_f16(hacc[ni], a, b[ni]);
        }

#pragma unroll
        for (int ni = 0; ni < 4; ni++) {
            int cl = cn + ni * 8 + gc;
            int cg = c * 64 + cl;
            float bb0 = b1[cg], bb1 = b1[cg + 1];
            float v0 = fmaxf(hacc[ni][0] + bb0, 0.0f);
            float v1 = fmaxf(hacc[ni][1] + bb1, 0.0f);
            float v2 = fmaxf(hacc[ni][2] + bb0, 0.0f);
            float v3 = fmaxf(hacc[ni][3] + bb1, 0.0f);
            *(unsigned*)&HS[(rm + gr) * SPH + cl] = pack2h(v0, v1);
            *(unsigned*)&HS[(rm + gr + 8) * SPH + cl] = pack2h(v2, v3);
        }
        __syncthreads();

        // GEMM2: acc2 += h @ W2c
#pragma unroll
        for (int kt = 0; kt < 4; kt++) {
            int kk = kt * 16;
            unsigned a[4], b[4][2];
            a[0] = *(unsigned*)&HS[(rm + gr) * SPH + kk + gc];
            a[1] = *(unsigned*)&HS[(rm + gr + 8) * SPH + kk + gc];
            a[2] = *(unsigned*)&HS[(rm + gr) * SPH + kk + gc + 8];
            a[3] = *(unsigned*)&HS[(rm + gr + 8) * SPH + kk + gc + 8];
#pragma unroll
            for (int ni = 0; ni < 4; ni++) {
                int n = cn + ni * 8 + gr;
                b[ni][0] = *(unsigned*)&W2s[n * SPH + kk + gc];
                b[ni][1] = *(unsigned*)&W2s[n * SPH + kk + gc + 8];
            }
#pragma unroll
            for (int ni = 0; ni < 4; ni++) mma_f16(acc2[ni], a, b[ni]);
        }
        __syncthreads();
    }

    // epilogue: + b2 -> buf, + residual, LN2
#pragma unroll
    for (int ni = 0; ni < 4; ni++) {
        int cc = cn + ni * 8 + gc;
        float b0 = b2[cc], b1v = b2[cc + 1];
        buf[(rm + gr) * 65 + cc] = acc2[ni][0] + b0;
        buf[(rm + gr) * 65 + cc + 1] = acc2[ni][1] + b1v;
        buf[(rm + gr + 8) * 65 + cc] = acc2[ni][2] + b0;
        buf[(rm + gr + 8) * 65 + cc + 1] = acc2[ni][3] + b1v;
    }
    __syncthreads();

    for (int rr = 0; rr < 8; rr++) {
        int row = w * 8 + rr;      // 16 warps x 8 rows = 128
        size_t go = (size_t)(row0 + row) * 64;
        float y0 = buf[row * 65 + lane] + xin[go + lane];
        float y1 = buf[row * 65 + lane + 32] + xin[go + lane + 32];
        float mean = warp_sum32(y0 + y1) * (1.0f / 64.0f);
        float d0 = y0 - mean, d1 = y1 - mean;
        float var = warp_sum32(d0 * d0 + d1 * d1) * (1.0f / 64.0f);
        float inv = rsqrtf(var + 1e-5f);
        float o0 = d0 * inv * ln_s[lane] + ln_b[lane];
        float o1 = d1 * inv * ln_s[lane + 32] + ln_b[lane + 32];
        x[go + lane] = o0;
        x[go + lane + 32] = o1;
        xh[go + lane] = __float2half_rn(o0);
        xh[go + lane + 32] = __float2half_rn(o1);
    }
}

// ---------------- head ----------------
__global__ void head_kernel(const float* __restrict__ x,
                            const float* __restrict__ W_head,
                            const float* __restrict__ b_head,
                            float* __restrict__ out)
{
    int b = blockIdx.x;
    int tid = threadIdx.x;  // 192
    int v = tid / 3, c = tid % 3;
    const float* row = x + ((size_t)(b * LL + (SS - 1) * VV + v)) * EE;
    float acc = b_head[c];
#pragma unroll
    for (int e = 0; e < EE; e++) acc += row[e] * W_head[e * 3 + c];
    out[b * (VV * 3) + tid] = acc;
}

// ---------------- launch ----------------
extern "C" void kernel_launch(void* const* d_in, const int* in_sizes, int n_in,
                              void* d_out, int out_size)
{
    const float* features    = (const float*)d_in[0];
    const int*   overlap_tag = (const int*)d_in[1];
    const int*   poi_id      = (const int*)d_in[2];
    const float* W_raw       = (const float*)d_in[3];
    const float* b_raw       = (const float*)d_in[4];
    const float* pos_tab     = (const float*)d_in[5];
    const float* type_tab    = (const float*)d_in[6];
    const float* poi_tab     = (const float*)d_in[7];
    const float* overlap_tab = (const float*)d_in[8];
    const float* W_comb      = (const float*)d_in[9];
    const float* b_comb      = (const float*)d_in[10];
    const float* Wqkv        = (const float*)d_in[11];
    const float* bqkv        = (const float*)d_in[12];
    const float* Wo          = (const float*)d_in[13];
    const float* bo          = (const float*)d_in[14];
    const float* ln1_s       = (const float*)d_in[15];
    const float* ln1_b       = (const float*)d_in[16];
    const float* W1          = (const float*)d_in[17];
    const float* b1          = (const float*)d_in[18];
    const float* W2          = (const float*)d_in[19];
    const float* b2          = (const float*)d_in[20];
    const float* ln2_s       = (const float*)d_in[21];
    const float* ln2_b       = (const float*)d_in[22];
    const float* W_head      = (const float*)d_in[23];
    const float* b_head      = (const float*)d_in[24];
    float* out = (float*)d_out;

    float *x, *qb, *kb, *vb;
    __half *xh, *attnh, *qkvT, *woT, *w1T, *w2T;
    unsigned char* zero;
    cudaGetSymbolAddress((void**)&x,     g_x);
    cudaGetSymbolAddress((void**)&xh,    g_xh);
    cudaGetSymbolAddress((void**)&qb,    g_q);
    cudaGetSymbolAddress((void**)&kb,    g_k);
    cudaGetSymbolAddress((void**)&vb,    g_v);
    cudaGetSymbolAddress((void**)&attnh, g_attnh);
    cudaGetSymbolAddress((void**)&zero,  g_zero);
    cudaGetSymbolAddress((void**)&qkvT,  g_qkvT);
    cudaGetSymbolAddress((void**)&woT,   g_woT);
    cudaGetSymbolAddress((void**)&w1T,   g_w1T);
    cudaGetSymbolAddress((void**)&w2T,   g_w2T);

    const int ATTN_SMEM = 16384 * 4 + 1024;
    cudaFuncSetAttribute(attn_kernel, cudaFuncAttributeMaxDynamicSharedMemorySize, ATTN_SMEM);
    cudaFuncSetAttribute(ffn_fused, cudaFuncAttributeMaxDynamicSharedMemorySize, FFN_SMEM);

    prep_weights<<<dim3(2048, 4), 256>>>(Wqkv, Wo, W1, W2);

    embed_kernel<<<ML, 64>>>(features, overlap_tag, poi_id, W_raw, b_raw,
                             pos_tab, type_tab, poi_tab, overlap_tab,
                             W_comb, b_comb, x, xh, zero);

    for (int l = 0; l < NL; l++) {
        gemm_qkv<<<dim3(3, ML / 128), 256>>>(
            xh, qkvT + l * 12288, bqkv + l * 192, qb, kb, vb);
        attn_kernel<<<BB * HH, 512, ATTN_SMEM>>>(qb, kb, vb, zero, attnh);
        gemm_wo_ln<<<ML / 64, 256>>>(
            attnh, woT + l * 4096, bo + l * EE, x, xh,
            ln1_s + l * EE, ln1_b + l * EE);
        ffn_fused<<<ML / 128, 512, FFN_SMEM>>>(
            x, xh, w1T + l * DFF * 64, w2T + l * DFF * 64,
            b1 + l * DFF, b2 + l * EE, x, xh,
            ln2_s + l * EE, ln2_b + l * EE);
    }

    head_kernel<<<BB, VV * 3>>>(x, W_head, b_head, out);
}

// round 7
// speedup vs baseline: 8.3554x; 1.1012x over previous
#include <cuda_runtime.h>
#include <cuda_fp16.h>
#include <math.h>

#define BB 16
#define SS 16
#define VV 64
#define EE 64
#define HH 8
#define NL 4
#define DFF 2048
#define LL 1024
#define ML (BB*LL)
#define SPH 72   // smem row stride in halves (64 data + 8 pad) = 144 bytes

// ---------------- scratch ----------------
__device__ float g_x[ML * EE];            // fp32 residual stream
__device__ __half g_xh[ML * EE];          // fp16 copy of x
__device__ float g_q[ML * EE];            // Q fp32 [B][H][L][8]
__device__ __half g_kh[ML * EE];          // K fp16 [B][H][L][8]
__device__ __half g_vh[ML * EE];          // V fp16 [B][H][L][8]
__device__ __half g_attnh[ML * EE];       // attention output (fp16)
__device__ unsigned char g_zero[ML];

// pre-converted transposed fp16 weights ([n][k])
__device__ __align__(256) __half g_qkvT[NL * 192 * 64];
__device__ __align__(256) __half g_woT[NL * 64 * 64];
__device__ __align__(256) __half g_w1T[NL * DFF * 64];
__device__ __align__(256) __half g_w2T[NL * DFF * 64];

// ---------------- helpers ----------------
__device__ __forceinline__ unsigned pack2h(float a, float b) {
    __half2 h = __floats2half2_rn(a, b);
    return *(unsigned*)&h;
}
__device__ __forceinline__ void mma_f16(float* c, const unsigned* a, const unsigned* b) {
    asm volatile(
        "mma.sync.aligned.m16n8k16.row.col.f32.f16.f16.f32 "
        "{%0,%1,%2,%3}, {%4,%5,%6,%7}, {%8,%9}, {%0,%1,%2,%3};\n"
        : "+f"(c[0]), "+f"(c[1]), "+f"(c[2]), "+f"(c[3])
        : "r"(a[0]), "r"(a[1]), "r"(a[2]), "r"(a[3]), "r"(b[0]), "r"(b[1]));
}
__device__ __forceinline__ float warp_sum32(float v) {
#pragma unroll
    for (int o = 16; o > 0; o >>= 1) v += __shfl_xor_sync(0xffffffffu, v, o);
    return v;
}
#define CP_ASYNC16(dst, src) \
    asm volatile("cp.async.ca.shared.global [%0], [%1], 16;\n" :: "r"(dst), "l"(src))
#define CP_COMMIT() asm volatile("cp.async.commit_group;\n")
#define CP_WAIT1()  asm volatile("cp.async.wait_group 1;\n")

// ---------------- weight prep ----------------
__global__ void prep_weights(const float* __restrict__ Wqkv,
                             const float* __restrict__ Wo,
                             const float* __restrict__ W1,
                             const float* __restrict__ W2)
{
    int t = blockIdx.x * 256 + threadIdx.x;
    int which = blockIdx.y;
    if (which == 0) {                       // qkv: [64k][192n] -> [n][k]
        if (t >= NL * 12288) return;
        int layer = t / 12288, rem = t % 12288, n = rem >> 6, k = rem & 63;
        g_qkvT[t] = __float2half_rn(Wqkv[(size_t)layer * 12288 + k * 192 + n]);
    } else if (which == 1) {                // wo: [64k][64n] -> [n][k]
        if (t >= NL * 4096) return;
        int layer = t / 4096, rem = t % 4096, n = rem >> 6, k = rem & 63;
        g_woT[t] = __float2half_rn(Wo[(size_t)layer * 4096 + k * 64 + n]);
    } else if (which == 2) {                // w1: [64k][2048n] -> [c][n][k]
        if (t >= NL * DFF * 64) return;
        int layer = t / (DFF * 64), rem = t % (DFF * 64), n = rem >> 6, k = rem & 63;
        g_w1T[t] = __float2half_rn(W1[(size_t)layer * DFF * 64 + k * DFF + n]);
    } else {                                // w2: [2048k][64n] -> [c][n][kl]
        if (t >= NL * DFF * 64) return;
        int layer = t / (DFF * 64), rem = t % (DFF * 64);
        int c = rem / 4096, w = rem % 4096, n = w >> 6, kl = w & 63;
        g_w2T[t] = __float2half_rn(W2[(size_t)layer * DFF * 64 + (c * 64 + kl) * 64 + n]);
    }
}

// ---------------- embed ----------------
__global__ void embed_kernel(const float* __restrict__ features,
                             const int* __restrict__ overlap_tag,
                             const int* __restrict__ poi_id,
                             const float* __restrict__ W_raw,
                             const float* __restrict__ b_raw,
                             const float* __restrict__ pos_tab,
                             const float* __restrict__ type_tab,
                             const float* __restrict__ poi_tab,
                             const float* __restrict__ overlap_tab,
                             const float* __restrict__ W_comb,
                             const float* __restrict__ b_comb,
                             float* __restrict__ x,
                             __half* __restrict__ xh,
                             unsigned char* __restrict__ zero_mask)
{
    int bl = blockIdx.x;
    int l  = bl & (LL - 1);
    int s  = l >> 6;
    int v  = l & 63;
    int tid = threadIdx.x;  // 64

    __shared__ float concat[80];
    const float* f = features + (size_t)bl * 3;
    float f0 = f[0], f1 = f[1], f2 = f[2];

    concat[tid] = f0 * W_raw[tid] + f1 * W_raw[64 + tid] + f2 * W_raw[128 + tid] + b_raw[tid];
    if (tid < 8) {
        int ov = overlap_tag[bl];
        concat[64 + tid] = (ov == 0) ? 0.0f : overlap_tab[ov * 8 + tid];
        int poi = poi_id[bl];
        concat[72 + tid] = (poi == 0) ? 0.0f : poi_tab[poi * 8 + tid];
    }
    if (tid == 0) zero_mask[bl] = (f0 + f1 + f2 == 0.0f) ? 1 : 0;
    __syncthreads();

    float acc = b_comb[tid];
#pragma unroll
    for (int j = 0; j < 80; j++) acc += concat[j] * W_comb[j * EE + tid];
    acc += pos_tab[s * EE + tid] + type_tab[v * EE + tid];
    x[(size_t)bl * EE + tid] = acc;
    xh[(size_t)bl * EE + tid] = __float2half_rn(acc);
}

// ---------------- QKV GEMM (fp16): Q -> fp32 permuted, K/V -> fp16 permuted ----------------
__global__ __launch_bounds__(256) void gemm_qkv(const __half* __restrict__ Xh,
                                                const __half* __restrict__ WT,
                                                const float* __restrict__ bias,
                                                float* __restrict__ Qo,
                                                __half* __restrict__ Ko,
                                                __half* __restrict__ Vo)
{
    __shared__ __align__(16) __half As[128 * SPH];
    __shared__ __align__(16) __half Ws[64 * SPH];

    int tid = threadIdx.x;
    int w = tid >> 5, lane = tid & 31;
    int wm = w >> 1, wn = w & 1;
    int rm = wm * 32, cn = wn * 32;
    int row0 = blockIdx.y * 128;
    int sel = blockIdx.x;
    int gr = lane >> 2, gc = (lane & 3) * 2;

    for (int i = tid; i < 1024; i += 256) {
        int r = i >> 3, seg = i & 7;
        *(uint4*)&As[r * SPH + seg * 8] = *(const uint4*)&Xh[(size_t)(row0 + r) * 64 + seg * 8];
    }
    const __half* src = WT + sel * 4096;
    for (int i = tid; i < 512; i += 256) {
        int n = i >> 3, seg = i & 7;
        *(uint4*)&Ws[n * SPH + seg * 8] = *(const uint4*)&src[n * 64 + seg * 8];
    }
    __syncthreads();

    float acc[2][4][4];
#pragma unroll
    for (int i = 0; i < 2; i++)
#pragma unroll
        for (int j = 0; j < 4; j++)
#pragma unroll
            for (int r = 0; r < 4; r++) acc[i][j][r] = 0.0f;

#pragma unroll
    for (int kt = 0; kt < 4; kt++) {
        int kk = kt * 16;
        unsigned a[2][4], b[4][2];
#pragma unroll
        for (int mi = 0; mi < 2; mi++) {
            int r = rm + mi * 16;
            a[mi][0] = *(unsigned*)&As[(r + gr) * SPH + kk + gc];
            a[mi][1] = *(unsigned*)&As[(r + gr + 8) * SPH + kk + gc];
            a[mi][2] = *(unsigned*)&As[(r + gr) * SPH + kk + gc + 8];
            a[mi][3] = *(unsigned*)&As[(r + gr + 8) * SPH + kk + gc + 8];
        }
#pragma unroll
        for (int ni = 0; ni < 4; ni++) {
            int n = cn + ni * 8 + gr;
            b[ni][0] = *(unsigned*)&Ws[n * SPH + kk + gc];
            b[ni][1] = *(unsigned*)&Ws[n * SPH + kk + gc + 8];
        }
#pragma unroll
        for (int mi = 0; mi < 2; mi++)
#pragma unroll
            for (int ni = 0; ni < 4; ni++)
                mma_f16(acc[mi][ni], a[mi], b[ni]);
    }

    int b = row0 >> 10;
    if (sel == 0) {
#pragma unroll
        for (int mi = 0; mi < 2; mi++) {
            int r0 = rm + mi * 16 + gr;
            int l0 = (row0 + r0) & (LL - 1);
#pragma unroll
            for (int ni = 0; ni < 4; ni++) {
                int loc = cn + ni * 8 + gc;
                int h = loc >> 3, d = loc & 7;
                float b0 = bias[loc], b1v = bias[loc + 1];
                size_t base = ((size_t)(b * 8 + h) * LL);
                *(float2*)&Qo[(base + l0) * 8 + d] =
                    make_float2(acc[mi][ni][0] + b0, acc[mi][ni][1] + b1v);
                *(float2*)&Qo[(base + l0 + 8) * 8 + d] =
                    make_float2(acc[mi][ni][2] + b0, acc[mi][ni][3] + b1v);
            }
        }
    } else {
        __half* outp = (sel == 1) ? Ko : Vo;
#pragma unroll
        for (int mi = 0; mi < 2; mi++) {
            int r0 = rm + mi * 16 + gr;
            int l0 = (row0 + r0) & (LL - 1);
#pragma unroll
            for (int ni = 0; ni < 4; ni++) {
                int loc = cn + ni * 8 + gc;
                int h = loc >> 3, d = loc & 7;
                float b0 = bias[sel * 64 + loc], b1v = bias[sel * 64 + loc + 1];
                size_t base = ((size_t)(b * 8 + h) * LL);
                *(unsigned*)&outp[(base + l0) * 8 + d] =
                    pack2h(acc[mi][ni][0] + b0, acc[mi][ni][1] + b1v);
                *(unsigned*)&outp[(base + l0 + 8) * 8 + d] =
                    pack2h(acc[mi][ni][2] + b0, acc[mi][ni][3] + b1v);
            }
        }
    }
}

// ---------------- attention: fp16 K/V smem, 2 adjacent queries/thread ----------------
#define ATTN_SMEM (32768 + 1024)

__device__ __forceinline__ void h8_to_f(const uint4& r, float* f) {
    const __half2* h2 = (const __half2*)&r;
    float2 t0 = __half22float2(h2[0]);
    float2 t1 = __half22float2(h2[1]);
    float2 t2 = __half22float2(h2[2]);
    float2 t3 = __half22float2(h2[3]);
    f[0] = t0.x; f[1] = t0.y; f[2] = t1.x; f[3] = t1.y;
    f[4] = t2.x; f[5] = t2.y; f[6] = t3.x; f[7] = t3.y;
}

__global__ __launch_bounds__(512) void attn_kernel(const float* __restrict__ Qg,
                                                   const __half* __restrict__ Kg,
                                                   const __half* __restrict__ Vg,
                                                   const unsigned char* __restrict__ zero_mask,
                                                   __half* __restrict__ out)
{
    extern __shared__ char smc[];
    __half* Ks = (__half*)smc;                       // 1024*8 halves = 16KB
    __half* Vs = (__half*)(smc + 16384);             // 16KB
    unsigned char* zs = (unsigned char*)(smc + 32768);

    int bh = blockIdx.x;                  // 128 blocks
    int b = bh >> 3, h = bh & 7;
    int tid = threadIdx.x;                // 512
    size_t base = (size_t)bh * LL * 8;

    for (int i = tid; i < 1024; i += 512) {
        ((uint4*)Ks)[i] = ((const uint4*)(Kg + base))[i];
        ((uint4*)Vs)[i] = ((const uint4*)(Vg + base))[i];
    }
    for (int i = tid; i < 1024; i += 512) zs[i] = zero_mask[b * LL + i];
    __syncthreads();

    const float scale = 0.35355339059327373f;
    int q0 = tid * 2, q1 = q0 + 1;        // same t-block
    int tq = q0 >> 6;
    int vq0 = q0 & 63, vq1 = vq0 + 1;

    float qa[8], qb[8];
    {
        float4 t0 = ((const float4*)(Qg + base + q0 * 8))[0];
        float4 t1 = ((const float4*)(Qg + base + q0 * 8))[1];
        qa[0] = t0.x * scale; qa[1] = t0.y * scale; qa[2] = t0.z * scale; qa[3] = t0.w * scale;
        qa[4] = t1.x * scale; qa[5] = t1.y * scale; qa[6] = t1.z * scale; qa[7] = t1.w * scale;
        t0 = ((const float4*)(Qg + base + q1 * 8))[0];
        t1 = ((const float4*)(Qg + base + q1 * 8))[1];
        qb[0] = t0.x * scale; qb[1] = t0.y * scale; qb[2] = t0.z * scale; qb[3] = t0.w * scale;
        qb[4] = t1.x * scale; qb[5] = t1.y * scale; qb[6] = t1.z * scale; qb[7] = t1.w * scale;
    }

    float sA = 0.0f, sB = 0.0f;
    float accA[8] = {}, accB[8] = {};

    // block-diagonal part: 64 shared keys (broadcast within warp)
    int kb = tq << 6;
#pragma unroll 4
    for (int j = 0; j < 64; j++) {
        int k = kb + j;
        uint4 kr = *(const uint4*)&Ks[k * 8];
        float kf[8]; h8_to_f(kr, kf);
        float dA = 0.0f, dB = 0.0f;
#pragma unroll
        for (int d = 0; d < 8; d++) { dA += qa[d] * kf[d]; dB += qb[d] * kf[d]; }
        float wA = __expf(dA), wB = __expf(dB);
        if (zs[k]) { wA = 0.0f; wB = 0.0f; }
        sA += wA; sB += wB;
        uint4 vr = *(const uint4*)&Vs[k * 8];
        float vf[8]; h8_to_f(vr, vf);
#pragma unroll
        for (int d = 0; d < 8; d++) { accA[d] += wA * vf[d]; accB[d] += wB * vf[d]; }
    }
    // same-type column for q0 (15 keys)
#pragma unroll
    for (int t = 0; t < 16; t++) {
        if (t == tq) continue;
        int k = (t << 6) + vq0;
        uint4 kr = *(const uint4*)&Ks[k * 8];
        float kf[8]; h8_to_f(kr, kf);
        float dA = 0.0f;
#pragma unroll
        for (int d = 0; d < 8; d++) dA += qa[d] * kf[d];
        float wA = __expf(dA);
        wA = zs[k] ? 0.0f : wA;
        sA += wA;
        uint4 vr = *(const uint4*)&Vs[k * 8];
        float vf[8]; h8_to_f(vr, vf);
#pragma unroll
        for (int d = 0; d < 8; d++) accA[d] += wA * vf[d];
    }
    // same-type column for q1 (15 keys)
#pragma unroll
    for (int t = 0; t < 16; t++) {
        if (t == tq) continue;
        int k = (t << 6) + vq1;
        uint4 kr = *(const uint4*)&Ks[k * 8];
        float kf[8]; h8_to_f(kr, kf);
        float dB = 0.0f;
#pragma unroll
        for (int d = 0; d < 8; d++) dB += qb[d] * kf[d];
        float wB = __expf(dB);
        wB = zs[k] ? 0.0f : wB;
        sB += wB;
        uint4 vr = *(const uint4*)&Vs[k * 8];
        float vf[8]; h8_to_f(vr, vf);
#pragma unroll
        for (int d = 0; d < 8; d++) accB[d] += wB * vf[d];
    }

    float invA = 1.0f / sA, invB = 1.0f / sB;
    __half* oA = out + ((size_t)(b * LL + q0)) * EE + h * 8;
    uint4 pk;
    pk.x = pack2h(accA[0] * invA, accA[1] * invA);
    pk.y = pack2h(accA[2] * invA, accA[3] * invA);
    pk.z = pack2h(accA[4] * invA, accA[5] * invA);
    pk.w = pack2h(accA[6] * invA, accA[7] * invA);
    *(uint4*)oA = pk;
    __half* oB = out + ((size_t)(b * LL + q1)) * EE + h * 8;
    pk.x = pack2h(accB[0] * invB, accB[1] * invB);
    pk.y = pack2h(accB[2] * invB, accB[3] * invB);
    pk.z = pack2h(accB[4] * invB, accB[5] * invB);
    pk.w = pack2h(accB[6] * invB, accB[7] * invB);
    *(uint4*)oB = pk;
}

// ---------------- Wo projection + residual + LN1 (fp16 GEMM) ----------------
__global__ __launch_bounds__(256) void gemm_wo_ln(const __half* __restrict__ A,
                                                  const __half* __restrict__ WT,
                                                  const float* __restrict__ bias,
                                                  float* __restrict__ x,
                                                  __half* __restrict__ xh,
                                                  const float* __restrict__ ln_s,
                                                  const float* __restrict__ ln_b)
{
    __shared__ __align__(16) __half As[64 * SPH];
    __shared__ __align__(16) __half Ws[64 * SPH];
    __shared__ float buf[64 * 65];

    int tid = threadIdx.x;
    int w = tid >> 5, lane = tid & 31;
    int wm = w >> 1, wn = w & 1;
    int rm = wm * 16, cn = wn * 32;
    int row0 = blockIdx.x * 64;
    int gr = lane >> 2, gc = (lane & 3) * 2;

    for (int i = tid; i < 512; i += 256) {
        int r = i >> 3, seg = i & 7;
        *(uint4*)&As[r * SPH + seg * 8] = *(const uint4*)&A[(size_t)(row0 + r) * 64 + seg * 8];
    }
    for (int i = tid; i < 512; i += 256) {
        int n = i >> 3, seg = i & 7;
        *(uint4*)&Ws[n * SPH + seg * 8] = *(const uint4*)&WT[n * 64 + seg * 8];
    }
    __syncthreads();

    float acc[4][4];
#pragma unroll
    for (int j = 0; j < 4; j++)
#pragma unroll
        for (int r = 0; r < 4; r++) acc[j][r] = 0.0f;

#pragma unroll
    for (int kt = 0; kt < 4; kt++) {
        int kk = kt * 16;
        unsigned a[4], b[4][2];
        a[0] = *(unsigned*)&As[(rm + gr) * SPH + kk + gc];
        a[1] = *(unsigned*)&As[(rm + gr + 8) * SPH + kk + gc];
        a[2] = *(unsigned*)&As[(rm + gr) * SPH + kk + gc + 8];
        a[3] = *(unsigned*)&As[(rm + gr + 8) * SPH + kk + gc + 8];
#pragma unroll
        for (int ni = 0; ni < 4; ni++) {
            int n = cn + ni * 8 + gr;
            b[ni][0] = *(unsigned*)&Ws[n * SPH + kk + gc];
            b[ni][1] = *(unsigned*)&Ws[n * SPH + kk + gc + 8];
        }
#pragma unroll
        for (int ni = 0; ni < 4; ni++) mma_f16(acc[ni], a, b[ni]);
    }

#pragma unroll
    for (int ni = 0; ni < 4; ni++) {
        int c = cn + ni * 8 + gc;
        float b0 = bias[c], b1v = bias[c + 1];
        buf[(rm + gr) * 65 + c] = acc[ni][0] + b0;
        buf[(rm + gr) * 65 + c + 1] = acc[ni][1] + b1v;
        buf[(rm + gr + 8) * 65 + c] = acc[ni][2] + b0;
        buf[(rm + gr + 8) * 65 + c + 1] = acc[ni][3] + b1v;
    }
    __syncthreads();

    for (int rr = 0; rr < 8; rr++) {
        int row = w * 8 + rr;
        size_t go = (size_t)(row0 + row) * 64;
        float y0 = buf[row * 65 + lane] + x[go + lane];
        float y1 = buf[row * 65 + lane + 32] + x[go + lane + 32];
        float mean = warp_sum32(y0 + y1) * (1.0f / 64.0f);
        float d0 = y0 - mean, d1 = y1 - mean;
        float var = warp_sum32(d0 * d0 + d1 * d1) * (1.0f / 64.0f);
        float inv = rsqrtf(var + 1e-5f);
        float o0 = d0 * inv * ln_s[lane] + ln_b[lane];
        float o1 = d1 * inv * ln_s[lane + 32] + ln_b[lane + 32];
        x[go + lane] = o0;
        x[go + lane + 32] = o1;
        xh[go + lane] = __float2half_rn(o0);
        xh[go + lane + 32] = __float2half_rn(o1);
    }
}

// ---------------- fused FFN (fp16), 128 rows/block, cp.async double-buffered ----------------
#define XS_OFF 0
#define HS_OFF 18432
#define WS_OFF 36864
#define WS_STRIDE 18432
#define FBUF_OFF 36864
#define FFN_SMEM 73728

__global__ __launch_bounds__(512) void ffn_fused(const float* __restrict__ xin,
                                                 const __half* __restrict__ xinh,
                                                 const __half* __restrict__ w1T,
                                                 const __half* __restrict__ w2T,
                                                 const float* __restrict__ b1,
                                                 const float* __restrict__ b2,
                                                 float* __restrict__ x,
                                                 __half* __restrict__ xh,
                                                 const float* __restrict__ ln_s,
                                                 const float* __restrict__ ln_b)
{
    extern __shared__ __align__(16) char sm[];
    __half* XS = (__half*)(sm + XS_OFF);
    __half* HS = (__half*)(sm + HS_OFF);
    float* buf = (float*)(sm + FBUF_OFF);
    unsigned smem_base = (unsigned)__cvta_generic_to_shared(sm);

    int tid = threadIdx.x;
    int w = tid >> 5, lane = tid & 31;
    int wm = w >> 1, wn = w & 1;
    int rm = wm * 16, cn = wn * 32;
    int row0 = blockIdx.x * 128;
    int gr = lane >> 2, gc = (lane & 3) * 2;

    // X tile: 128 rows x 64 halves via cp.async (2 x 16B per thread)
    {
        unsigned xs = smem_base + XS_OFF;
        int r = tid >> 2, seg0 = (tid & 3) * 2;
        const __half* src = xinh + (size_t)(row0 + r) * 64;
        CP_ASYNC16(xs + r * 144 + seg0 * 16, src + seg0 * 8);
        CP_ASYNC16(xs + r * 144 + (seg0 + 1) * 16, src + (seg0 + 1) * 8);
    }

    // weight loader indices (512 threads = 64 rows x 8 segs)
    int wr = tid >> 3, wseg = tid & 7;
    unsigned wdst = (unsigned)(wr * 144 + wseg * 16);
    int wsrc = wr * 64 + wseg * 8;

    float acc2[4][4];
#pragma unroll
    for (int j = 0; j < 4; j++)
#pragma unroll
        for (int r = 0; r < 4; r++) acc2[j][r] = 0.0f;

    // preload chunk 0 into stage 0
    {
        unsigned st = smem_base + WS_OFF;
        CP_ASYNC16(st + wdst, w1T + wsrc);
        CP_ASYNC16(st + 9216 + wdst, w2T + wsrc);
    }
    CP_COMMIT();

    for (int c = 0; c < 32; c++) {
        int s = c & 1;
        if (c + 1 < 32) {
            unsigned st = smem_base + WS_OFF + (s ^ 1) * WS_STRIDE;
            int src = (c + 1) * 4096 + wsrc;
            CP_ASYNC16(st + wdst, w1T + src);
            CP_ASYNC16(st + 9216 + wdst, w2T + src);
        }
        CP_COMMIT();
        CP_WAIT1();
        __syncthreads();

        __half* W1s = (__half*)(sm + WS_OFF + s * WS_STRIDE);
        __half* W2s = (__half*)(sm + WS_OFF + s * WS_STRIDE + 9216);

        // GEMM1: h = relu(x @ W1c + b1c), warp tile 16x32
        float hacc[4][4];
#pragma unroll
        for (int j = 0; j < 4; j++)
#pragma unroll
            for (int r = 0; r < 4; r++) hacc[j][r] = 0.0f;

#pragma unroll
        for (int kt = 0; kt < 4; kt++) {
            int kk = kt * 16;
            unsigned a[4], b[4][2];
            a[0] = *(unsigned*)&XS[(rm + gr) * SPH + kk + gc];
            a[1] = *(unsigned*)&XS[(rm + gr + 8) * SPH + kk + gc];
            a[2] = *(unsigned*)&XS[(rm + gr) * SPH + kk + gc + 8];
            a[3] = *(unsigned*)&XS[(rm + gr + 8) * SPH + kk + gc + 8];
#pragma unroll
            for (int ni = 0; ni < 4; ni++) {
                int n = cn + ni * 8 + gr;
                b[ni][0] = *(unsigned*)&W1s[n * SPH + kk + gc];
                b[ni][1] = *(unsigned*)&W1s[n * SPH + kk + gc + 8];
            }
#pragma unroll
            for (int ni = 0; ni < 4; ni++) mma_f16(hacc[ni], a, b[ni]);
        }

#pragma unroll
        for (int ni = 0; ni < 4; ni++) {
            int cl = cn + ni * 8 + gc;
            int cg = c * 64 + cl;
            float bb0 = b1[cg], bb1 = b1[cg + 1];
            float v0 = fmaxf(hacc[ni][0] + bb0, 0.0f);
            float v1 = fmaxf(hacc[ni][1] + bb1, 0.0f);
            float v2 = fmaxf(hacc[ni][2] + bb0, 0.0f);
            float v3 = fmaxf(hacc[ni][3] + bb1, 0.0f);
            *(unsigned*)&HS[(rm + gr) * SPH + cl] = pack2h(v0, v1);
            *(unsigned*)&HS[(rm + gr + 8) * SPH + cl] = pack2h(v2, v3);
        }
        __syncthreads();

        // GEMM2: acc2 += h @ W2c
#pragma unroll
        for (int kt = 0; kt < 4; kt++) {
            int kk = kt * 16;
            unsigned a[4], b[4][2];
            a[0] = *(unsigned*)&HS[(rm + gr) * SPH + kk + gc];
            a[1] = *(unsigned*)&HS[(rm + gr + 8) * SPH + kk + gc];
            a[2] = *(unsigned*)&HS[(rm + gr) * SPH + kk + gc + 8];
            a[3] = *(unsigned*)&HS[(rm + gr + 8) * SPH + kk + gc + 8];
#pragma unroll
            for (int ni = 0; ni < 4; ni++) {
                int n = cn + ni * 8 + gr;
                b[ni][0] = *(unsigned*)&W2s[n * SPH + kk + gc];
                b[ni][1] = *(unsigned*)&W2s[n * SPH + kk + gc + 8];
            }
#pragma unroll
            for (int ni = 0; ni < 4; ni++) mma_f16(acc2[ni], a, b[ni]);
        }
        __syncthreads();
    }

    // epilogue: + b2 -> buf, + residual, LN2
#pragma unroll
    for (int ni = 0; ni < 4; ni++) {
        int cc = cn + ni * 8 + gc;
        float b0 = b2[cc], b1v = b2[cc + 1];
        buf[(rm + gr) * 65 + cc] = acc2[ni][0] + b0;
        buf[(rm + gr) * 65 + cc + 1] = acc2[ni][1] + b1v;
        buf[(rm + gr + 8) * 65 + cc] = acc2[ni][2] + b0;
        buf[(rm + gr + 8) * 65 + cc + 1] = acc2[ni][3] + b1v;
    }
    __syncthreads();

    for (int rr = 0; rr < 8; rr++) {
        int row = w * 8 + rr;      // 16 warps x 8 rows = 128
        size_t go = (size_t)(row0 + row) * 64;
        float y0 = buf[row * 65 + lane] + xin[go + lane];
        float y1 = buf[row * 65 + lane + 32] + xin[go + lane + 32];
        float mean = warp_sum32(y0 + y1) * (1.0f / 64.0f);
        float d0 = y0 - mean, d1 = y1 - mean;
        float var = warp_sum32(d0 * d0 + d1 * d1) * (1.0f / 64.0f);
        float inv = rsqrtf(var + 1e-5f);
        float o0 = d0 * inv * ln_s[lane] + ln_b[lane];
        float o1 = d1 * inv * ln_s[lane + 32] + ln_b[lane + 32];
        x[go + lane] = o0;
        x[go + lane + 32] = o1;
        xh[go + lane] = __float2half_rn(o0);
        xh[go + lane + 32] = __float2half_rn(o1);
    }
}

// ---------------- head ----------------
__global__ void head_kernel(const float* __restrict__ x,
                            const float* __restrict__ W_head,
                            const float* __restrict__ b_head,
                            float* __restrict__ out)
{
    int b = blockIdx.x;
    int tid = threadIdx.x;  // 192
    int v = tid / 3, c = tid % 3;
    const float* row = x + ((size_t)(b * LL + (SS - 1) * VV + v)) * EE;
    float acc = b_head[c];
#pragma unroll
    for (int e = 0; e < EE; e++) acc += row[e] * W_head[e * 3 + c];
    out[b * (VV * 3) + tid] = acc;
}

// ---------------- launch ----------------
extern "C" void kernel_launch(void* const* d_in, const int* in_sizes, int n_in,
                              void* d_out, int out_size)
{
    const float* features    = (const float*)d_in[0];
    const int*   overlap_tag = (const int*)d_in[1];
    const int*   poi_id      = (const int*)d_in[2];
    const float* W_raw       = (const float*)d_in[3];
    const float* b_raw       = (const float*)d_in[4];
    const float* pos_tab     = (const float*)d_in[5];
    const float* type_tab    = (const float*)d_in[6];
    const float* poi_tab     = (const float*)d_in[7];
    const float* overlap_tab = (const float*)d_in[8];
    const float* W_comb      = (const float*)d_in[9];
    const float* b_comb      = (const float*)d_in[10];
    const float* Wqkv        = (const float*)d_in[11];
    const float* bqkv        = (const float*)d_in[12];
    const float* Wo          = (const float*)d_in[13];
    const float* bo          = (const float*)d_in[14];
    const float* ln1_s       = (const float*)d_in[15];
    const float* ln1_b       = (const float*)d_in[16];
    const float* W1          = (const float*)d_in[17];
    const float* b1          = (const float*)d_in[18];
    const float* W2          = (const float*)d_in[19];
    const float* b2          = (const float*)d_in[20];
    const float* ln2_s       = (const float*)d_in[21];
    const float* ln2_b       = (const float*)d_in[22];
    const float* W_head      = (const float*)d_in[23];
    const float* b_head      = (const float*)d_in[24];
    float* out = (float*)d_out;

    float *x, *qb;
    __half *xh, *kb, *vb, *attnh, *qkvT, *woT, *w1T, *w2T;
    unsigned char* zero;
    cudaGetSymbolAddress((void**)&x,     g_x);
    cudaGetSymbolAddress((void**)&xh,    g_xh);
    cudaGetSymbolAddress((void**)&qb,    g_q);
    cudaGetSymbolAddress((void**)&kb,    g_kh);
    cudaGetSymbolAddress((void**)&vb,    g_vh);
    cudaGetSymbolAddress((void**)&attnh, g_attnh);
    cudaGetSymbolAddress((void**)&zero,  g_zero);
    cudaGetSymbolAddress((void**)&qkvT,  g_qkvT);
    cudaGetSymbolAddress((void**)&woT,   g_woT);
    cudaGetSymbolAddress((void**)&w1T,   g_w1T);
    cudaGetSymbolAddress((void**)&w2T,   g_w2T);

    cudaFuncSetAttribute(attn_kernel, cudaFuncAttributeMaxDynamicSharedMemorySize, ATTN_SMEM);
    cudaFuncSetAttribute(ffn_fused, cudaFuncAttributeMaxDynamicSharedMemorySize, FFN_SMEM);

    prep_weights<<<dim3(2048, 4), 256>>>(Wqkv, Wo, W1, W2);

    embed_kernel<<<ML, 64>>>(features, overlap_tag, poi_id, W_raw, b_raw,
                             pos_tab, type_tab, poi_tab, overlap_tab,
                             W_comb, b_comb, x, xh, zero);

    for (int l = 0; l < NL; l++) {
        gemm_qkv<<<dim3(3, ML / 128), 256>>>(
            xh, qkvT + l * 12288, bqkv + l * 192, qb, kb, vb);
        attn_kernel<<<BB * HH, 512, ATTN_SMEM>>>(qb, kb, vb, zero, attnh);
        gemm_wo_ln<<<ML / 64, 256>>>(
            attnh, woT + l * 4096, bo + l * EE, x, xh,
            ln1_s + l * EE, ln1_b + l * EE);
        ffn_fused<<<ML / 128, 512, FFN_SMEM>>>(
            x, xh, w1T + l * DFF * 64, w2T + l * DFF * 64,
            b1 + l * DFF, b2 + l * EE, x, xh,
            ln2_s + l * EE, ln2_b + l * EE);
    }

    head_kernel<<<BB, VV * 3>>>(x, W_head, b_head, out);
}